// round 13
// baseline (speedup 1.0000x reference)
#include <cuda_runtime.h>
#include <cuda_bf16.h>
#include <cstdint>

#define B_ 2048
#define S_ 50
#define D_ 64
#define L_ 500
#define K_ 4
#define N_ 100000
#define TAU_ 0.1f
#define LN_EPS 1e-12f
#define ROWS_ (B_ * S_)

// v_u in MMA-fragment order (hi/lo): [rowtile 128][kk 4][lane 32] each uint4
__device__ uint4 g_vufh[128 * 4 * 32];
__device__ uint4 g_vufl[128 * 4 * 32];
// rowgemm outputs
__device__ float g_aklog[K_ * ROWS_];
__device__ float g_logit[ROWS_];
__device__ float g_w3n[ROWS_ * D_];
// zu / su
__device__ float g_zu[B_ * D_];
__device__ float g_su[B_ * L_];

__device__ __forceinline__ float warpsum(float v) {
#pragma unroll
    for (int o = 16; o; o >>= 1) v += __shfl_xor_sync(0xffffffffu, v, o);
    return v;
}
__device__ __forceinline__ float warpmax(float v) {
#pragma unroll
    for (int o = 16; o; o >>= 1) v = fmaxf(v, __shfl_xor_sync(0xffffffffu, v, o));
    return v;
}
__device__ __forceinline__ uint32_t pack_bf16(float a, float b) {
    __nv_bfloat162 t = __floats2bfloat162_rn(a, b);
    return *reinterpret_cast<uint32_t*>(&t);
}

#define MMA_BF16(d0,d1,d2,d3,a0,a1,a2,a3,b0,b1)                              \
    asm volatile("mma.sync.aligned.m16n8k16.row.col.f32.bf16.bf16.f32 "      \
        "{%0,%1,%2,%3}, {%4,%5,%6,%7}, {%8,%9}, {%0,%1,%2,%3};"              \
        : "+f"(d0), "+f"(d1), "+f"(d2), "+f"(d3)                             \
        : "r"(a0), "r"(a1), "r"(a2), "r"(a3), "r"(b0), "r"(b1))
#define LDSM4(r0,r1,r2,r3,addr)                                              \
    asm volatile("ldmatrix.sync.aligned.m8n8.x4.shared.b16 {%0,%1,%2,%3}, [%4];" \
        : "=r"(r0), "=r"(r1), "=r"(r2), "=r"(r3) : "r"(addr))

// ---------------------------------------------------------------------------
// Kernel 0: rowgemm (unchanged)
// ---------------------------------------------------------------------------
#define ASTR 72
__global__ __launch_bounds__(256) void rowgemm_kernel(
    const int* __restrict__ item_seq, const float* __restrict__ item_emb,
    const float* __restrict__ wk1, const float* __restrict__ wk2,
    const float* __restrict__ w1, const float* __restrict__ w2,
    const float* __restrict__ w3)
{
    __shared__ __align__(16) __nv_bfloat16 Ah[128 * ASTR];
    __shared__ __align__(16) __nv_bfloat16 Al[128 * ASTR];
    __shared__ __align__(16) __nv_bfloat16 Bh[D_ * ASTR];
    __shared__ __align__(16) __nv_bfloat16 Bl[D_ * ASTR];
    __shared__ float wvec[D_];

    const int tid = threadIdx.x, lane = tid & 31, w = tid >> 5;
    const int rbase = blockIdx.x * 128;
    {
        int r = tid >> 1, h = tid & 1;
        int it = __ldg(&item_seq[rbase + r]);
        const float4* ep = reinterpret_cast<const float4*>(item_emb + (size_t)it * D_) + h * 8;
        uint32_t* dh = reinterpret_cast<uint32_t*>(Ah + r * ASTR + h * 32);
        uint32_t* dl = reinterpret_cast<uint32_t*>(Al + r * ASTR + h * 32);
#pragma unroll
        for (int i = 0; i < 8; i++) {
            float4 f = __ldg(&ep[i]);
            uint32_t h0 = pack_bf16(f.x, f.y), h1 = pack_bf16(f.z, f.w);
            __nv_bfloat162 b0 = *reinterpret_cast<__nv_bfloat162*>(&h0);
            __nv_bfloat162 b1 = *reinterpret_cast<__nv_bfloat162*>(&h1);
            dh[2*i] = h0; dh[2*i+1] = h1;
            dl[2*i]   = pack_bf16(f.x - __bfloat162float(b0.x), f.y - __bfloat162float(b0.y));
            dl[2*i+1] = pack_bf16(f.z - __bfloat162float(b1.x), f.w - __bfloat162float(b1.y));
        }
    }
    const int lg = lane >> 2, q = lane & 3;
    const int rig = lane & 7, mcode = lane >> 3;
    const int j_off = mcode >> 1, khalf = mcode & 1;
    const int mbase = w * 16;
    uint32_t aBh = (uint32_t)__cvta_generic_to_shared(Ah)
                 + ((mbase + (lane & 7) + ((lane >> 3) & 1) * 8) * ASTR + ((lane >> 4) * 8)) * 2;
    uint32_t aBl = (uint32_t)__cvta_generic_to_shared(Al)
                 + ((mbase + (lane & 7) + ((lane >> 3) & 1) * 8) * ASTR + ((lane >> 4) * 8)) * 2;
    uint32_t bBh = (uint32_t)__cvta_generic_to_shared(Bh)
                 + ((j_off * 8 + rig) * ASTR + khalf * 8) * 2;
    uint32_t bBl = (uint32_t)__cvta_generic_to_shared(Bl)
                 + ((j_off * 8 + rig) * ASTR + khalf * 8) * 2;
    const int r0g = rbase + mbase + lg, r1g = r0g + 8;

    for (int widx = 0; widx < 6; widx++) {
        __syncthreads();
        const float* W = (widx < 4) ? (wk1 + widx * D_ * D_) : (widx == 4 ? w1 : w3);
        const float4* Wv = reinterpret_cast<const float4*>(W);
#pragma unroll
        for (int i = 0; i < 4; i++) {
            int f = tid + i * 256;
            float4 v = __ldg(&Wv[f]);
            int d = f >> 4, e0 = (f & 15) * 4;
            const float* vv = &v.x;
#pragma unroll
            for (int j = 0; j < 4; j++) {
                float val = vv[j];
                __nv_bfloat16 h = __float2bfloat16(val);
                Bh[(e0 + j) * ASTR + d] = h;
                Bl[(e0 + j) * ASTR + d] = __float2bfloat16(val - __bfloat162float(h));
            }
        }
        if (tid < D_) {
            if (widx < 4)       wvec[tid] = __ldg(&wk2[widx * D_ + tid]);
            else if (widx == 4) wvec[tid] = __ldg(&w2[tid]);
        }
        __syncthreads();

        float acc[8][4];
#pragma unroll
        for (int j = 0; j < 8; j++) { acc[j][0]=0.f; acc[j][1]=0.f; acc[j][2]=0.f; acc[j][3]=0.f; }
#pragma unroll
        for (int kk = 0; kk < 4; kk++) {
            uint32_t ah0,ah1,ah2,ah3, al0,al1,al2,al3;
            LDSM4(ah0,ah1,ah2,ah3, aBh + kk * 32);
            LDSM4(al0,al1,al2,al3, aBl + kk * 32);
#pragma unroll
            for (int p = 0; p < 4; p++) {
                uint32_t b0h,b1h,b2h,b3h, b0l,b1l,b2l,b3l;
                uint32_t off = (uint32_t)(p * 16 * ASTR * 2 + kk * 32);
                LDSM4(b0h,b1h,b2h,b3h, bBh + off);
                LDSM4(b0l,b1l,b2l,b3l, bBl + off);
                int j0 = 2 * p, j1 = 2 * p + 1;
                MMA_BF16(acc[j0][0],acc[j0][1],acc[j0][2],acc[j0][3], ah0,ah1,ah2,ah3, b0h,b1h);
                MMA_BF16(acc[j0][0],acc[j0][1],acc[j0][2],acc[j0][3], ah0,ah1,ah2,ah3, b0l,b1l);
                MMA_BF16(acc[j0][0],acc[j0][1],acc[j0][2],acc[j0][3], al0,al1,al2,al3, b0h,b1h);
                MMA_BF16(acc[j1][0],acc[j1][1],acc[j1][2],acc[j1][3], ah0,ah1,ah2,ah3, b2h,b3h);
                MMA_BF16(acc[j1][0],acc[j1][1],acc[j1][2],acc[j1][3], ah0,ah1,ah2,ah3, b2l,b3l);
                MMA_BF16(acc[j1][0],acc[j1][1],acc[j1][2],acc[j1][3], al0,al1,al2,al3, b2h,b3h);
            }
        }
        if (widx < 5) {
            float s0 = 0.f, s1 = 0.f;
#pragma unroll
            for (int j = 0; j < 8; j++) {
                int e0 = j * 8 + 2 * q;
                float w0 = wvec[e0], w1v = wvec[e0 + 1];
                s0 += tanhf(acc[j][0]) * w0 + tanhf(acc[j][1]) * w1v;
                s1 += tanhf(acc[j][2]) * w0 + tanhf(acc[j][3]) * w1v;
            }
            s0 += __shfl_xor_sync(0xffffffffu, s0, 1);
            s0 += __shfl_xor_sync(0xffffffffu, s0, 2);
            s1 += __shfl_xor_sync(0xffffffffu, s1, 1);
            s1 += __shfl_xor_sync(0xffffffffu, s1, 2);
            if (q == 0) {
                if (widx < 4) { g_aklog[widx * ROWS_ + r0g] = s0; g_aklog[widx * ROWS_ + r1g] = s1; }
                else          { g_logit[r0g] = s0; g_logit[r1g] = s1; }
            }
        } else {
            float n0 = 0.f, n1 = 0.f;
#pragma unroll
            for (int j = 0; j < 8; j++) {
                n0 += acc[j][0]*acc[j][0] + acc[j][1]*acc[j][1];
                n1 += acc[j][2]*acc[j][2] + acc[j][3]*acc[j][3];
            }
            n0 += __shfl_xor_sync(0xffffffffu, n0, 1);
            n0 += __shfl_xor_sync(0xffffffffu, n0, 2);
            n1 += __shfl_xor_sync(0xffffffffu, n1, 1);
            n1 += __shfl_xor_sync(0xffffffffu, n1, 2);
            float inv0 = 1.f / fmaxf(sqrtf(n0), 1e-12f);
            float inv1 = 1.f / fmaxf(sqrtf(n1), 1e-12f);
#pragma unroll
            for (int j = 0; j < 8; j++) {
                int c0 = j * 8 + 2 * q;
                *reinterpret_cast<float2*>(g_w3n + (size_t)r0g * D_ + c0) =
                    make_float2(acc[j][0] * inv0, acc[j][1] * inv0);
                *reinterpret_cast<float2*>(g_w3n + (size_t)r1g * D_ + c0) =
                    make_float2(acc[j][2] * inv1, acc[j][3] * inv1);
            }
        }
    }
}

// ---------------------------------------------------------------------------
// Kernel 1: zu (unchanged)
// ---------------------------------------------------------------------------
__global__ __launch_bounds__(64) void zu_kernel(
    const int* __restrict__ item_seq, const float* __restrict__ item_emb)
{
    __shared__ float aw[S_];
    __shared__ int   seqs[S_];
    __shared__ __align__(16) float4 part[4][16];
    const int b = blockIdx.x, tid = threadIdx.x;
    if (tid < S_) seqs[tid] = __ldg(&item_seq[b * S_ + tid]);
    if (tid < 32) {
        const float* lp = g_logit + b * S_;
        float v0 = (tid < S_) ? lp[tid] : -1e30f;
        float v1 = (tid + 32 < S_) ? lp[tid + 32] : -1e30f;
        float m = warpmax(fmaxf(v0, v1));
        float e0 = (tid < S_) ? expf(v0 - m) : 0.f;
        float e1 = (tid + 32 < S_) ? expf(v1 - m) : 0.f;
        float inv = 1.f / warpsum(e0 + e1);
        if (tid < S_) aw[tid] = e0 * inv;
        if (tid + 32 < S_) aw[tid + 32] = e1 * inv;
    }
    __syncthreads();
    int qd = tid & 15, strip = tid >> 4;
    float4 acc = make_float4(0.f, 0.f, 0.f, 0.f);
    for (int s = strip; s < S_; s += 4) {
        const float4* xp = reinterpret_cast<const float4*>(item_emb + (size_t)seqs[s] * D_);
        float4 x = __ldg(&xp[qd]);
        float a = aw[s];
        acc.x = fmaf(a, x.x, acc.x); acc.y = fmaf(a, x.y, acc.y);
        acc.z = fmaf(a, x.z, acc.z); acc.w = fmaf(a, x.w, acc.w);
    }
    part[strip][qd] = acc;
    __syncthreads();
    if (tid < 16) {
        float4 a = part[0][tid], b1 = part[1][tid], c = part[2][tid], d = part[3][tid];
        reinterpret_cast<float4*>(g_zu + b * D_)[tid] =
            make_float4(a.x+b1.x+c.x+d.x, a.y+b1.y+c.y+d.y, a.z+b1.z+c.z+d.z, a.w+b1.w+c.w+d.w);
    }
}

// ---------------------------------------------------------------------------
// Kernel 2: su (unchanged)
// ---------------------------------------------------------------------------
__global__ __launch_bounds__(256) void su_kernel(const float* __restrict__ Cg)
{
    __shared__ __align__(16) float Zs[16][D_];
    const int tid = threadIdx.x, bbase = blockIdx.x * 16;
    for (int i = tid; i < 16 * 16; i += 256) {
        int j = i >> 4, q = i & 15;
        reinterpret_cast<float4*>(&Zs[j][0])[q] =
            reinterpret_cast<const float4*>(g_zu + (bbase + j) * D_)[q];
    }
    __syncthreads();
    for (int l = tid; l < L_; l += 256) {
        float acc[16];
#pragma unroll
        for (int j = 0; j < 16; j++) acc[j] = 0.f;
        const float4* cr = reinterpret_cast<const float4*>(Cg + l * D_);
#pragma unroll
        for (int dq = 0; dq < 16; dq++) {
            float4 c = __ldg(&cr[dq]);
#pragma unroll
            for (int j = 0; j < 16; j++) {
                acc[j] = fmaf(c.x, Zs[j][4*dq],   acc[j]);
                acc[j] = fmaf(c.y, Zs[j][4*dq+1], acc[j]);
                acc[j] = fmaf(c.z, Zs[j][4*dq+2], acc[j]);
                acc[j] = fmaf(c.w, Zs[j][4*dq+3], acc[j]);
            }
        }
#pragma unroll
        for (int j = 0; j < 16; j++) g_su[(bbase + j) * L_ + l] = acc[j];
    }
}

// ---------------------------------------------------------------------------
// Kernel 3: head (unchanged)
// ---------------------------------------------------------------------------
__global__ __launch_bounds__(256) void head_kernel(
    const int* __restrict__ item_seq, const float* __restrict__ item_emb,
    const float* __restrict__ Cg,
    const float* __restrict__ w3, const float* __restrict__ w4,
    const float* __restrict__ ln2w, const float* __restrict__ ln2b,
    const float* __restrict__ ln4w, const float* __restrict__ ln4b)
{
    __shared__ __align__(16) float xu[S_][D_];
    __shared__ __align__(16) float buf2[S_][D_];
    __shared__ int   seqs[S_];
    __shared__ float logit[S_];
    __shared__ float aw[S_];
    __shared__ __align__(16) float su[L_];
    __shared__ float selv[K_];
    __shared__ int   seli[K_];
    __shared__ float stopv[K_];
    __shared__ int   sidx[K_];
    __shared__ __align__(16) float Cu[K_][D_];
    __shared__ __align__(16) float Cun[K_][D_];
    __shared__ __align__(16) float Pktb[S_][K_];
    __shared__ float mulp[K_][S_];
    __shared__ __align__(16) float delta[K_][D_];
    __shared__ float nrm2[K_];
    __shared__ float capt[D_];
    __shared__ float ekw[K_];
    __shared__ float vstage[D_];

    const int b = blockIdx.x, tid = threadIdx.x, lane = tid & 31, w = tid >> 5;

    if (tid < S_) seqs[tid] = __ldg(&item_seq[b * S_ + tid]);
    if (tid < 125)
        reinterpret_cast<float4*>(su)[tid] =
            __ldg(&reinterpret_cast<const float4*>(g_su + b * L_)[tid]);
    __syncthreads();
    {
        for (int i = tid; i < S_ * 16; i += 256) {
            int s = i >> 4, q = i & 15;
            const float4* ep = reinterpret_cast<const float4*>(item_emb + (size_t)seqs[s] * D_);
            reinterpret_cast<float4*>(&xu[s][0])[q] = __ldg(&ep[q]);
        }
        const float4* wp = reinterpret_cast<const float4*>(g_w3n + (size_t)b * S_ * D_);
        for (int i = tid; i < S_ * 16; i += 256) {
            int s = i >> 4, q = i & 15;
            reinterpret_cast<float4*>(&buf2[s][0])[q] = __ldg(&wp[i]);
        }
    }
    __syncthreads();

    if (w == 0) {
        for (int r = 0; r < K_; r++) {
            float mv = -1e30f; int mi = -1;
            for (int l = lane; l < L_; l += 32) {
                bool skip = false;
#pragma unroll
                for (int t = 0; t < K_; t++)
                    if (t < r && seli[t] == l) skip = true;
                float v = su[l];
                if (!skip && (v > mv || (v == mv && l > mi))) { mv = v; mi = l; }
            }
#pragma unroll
            for (int o = 16; o; o >>= 1) {
                float ov = __shfl_xor_sync(0xffffffffu, mv, o);
                int   oi = __shfl_xor_sync(0xffffffffu, mi, o);
                if (ov > mv || (ov == mv && oi > mi)) { mv = ov; mi = oi; }
            }
            if (lane == 0) { seli[r] = mi; selv[r] = mv; }
            __syncwarp();
        }
        if (lane < K_) { sidx[lane] = seli[K_ - 1 - lane]; stopv[lane] = selv[K_ - 1 - lane]; }
    }
    __syncthreads();

    if (w < K_) {
        int k = w;
        float sg = 1.f / (1.f + expf(-stopv[k]));
        const float* cr = Cg + sidx[k] * D_;
        float v0 = __ldg(&cr[lane]) * sg;
        float v1 = __ldg(&cr[lane + 32]) * sg;
        Cu[k][lane] = v0; Cu[k][lane + 32] = v1;
        float mean = warpsum(v0 + v1) * (1.f / 64.f);
        float d0 = v0 - mean, d1 = v1 - mean;
        float var = warpsum(d0 * d0 + d1 * d1) * (1.f / 64.f);
        float inv = rsqrtf(var + LN_EPS);
        Cun[k][lane]      = d0 * inv * __ldg(&ln2w[lane])      + __ldg(&ln2b[lane]);
        Cun[k][lane + 32] = d1 * inv * __ldg(&ln2w[lane + 32]) + __ldg(&ln2b[lane + 32]);
    }
    __syncthreads();

    if (tid < S_ * K_) {
        int s = tid >> 2, k = tid & 3;
        const float4* bp = reinterpret_cast<const float4*>(&buf2[s][0]);
        const float4* cp = reinterpret_cast<const float4*>(&Cun[k][0]);
        float acc = 0.f;
#pragma unroll
        for (int q = 0; q < 16; q++) {
            float4 x = bp[q], c = cp[q];
            acc += x.x*c.x + x.y*c.y + x.z*c.z + x.w*c.w;
        }
        Pktb[s][k] = acc;
    }
    __syncthreads();
    if (tid < S_) {
        float v0 = Pktb[tid][0], v1 = Pktb[tid][1], v2 = Pktb[tid][2], v3 = Pktb[tid][3];
        float m = fmaxf(fmaxf(v0, v1), fmaxf(v2, v3));
        float e0 = expf(v0 - m), e1 = expf(v1 - m), e2 = expf(v2 - m), e3 = expf(v3 - m);
        float inv = 1.f / (e0 + e1 + e2 + e3);
        Pktb[tid][0] = e0 * inv; Pktb[tid][1] = e1 * inv;
        Pktb[tid][2] = e2 * inv; Pktb[tid][3] = e3 * inv;
    }
    __syncthreads();

    if (w < K_) {
        int k = w;
        const float* akr = g_aklog + k * ROWS_ + b * S_;
        float v0 = (lane < S_) ? akr[lane] : -1e30f;
        float v1 = (lane + 32 < S_) ? akr[lane + 32] : -1e30f;
        float m = warpmax(fmaxf(v0, v1));
        float e0 = (lane < S_) ? expf(v0 - m) : 0.f;
        float e1 = (lane + 32 < S_) ? expf(v1 - m) : 0.f;
        float inv = 1.f / warpsum(e0 + e1);
        if (lane < S_) mulp[k][lane] = Pktb[lane][k] * e0 * inv;
        if (lane + 32 < S_) mulp[k][lane + 32] = Pktb[lane + 32][k] * e1 * inv;
    }
    __syncthreads();

    if (tid < 128) {
        int k = tid >> 5, d2 = tid & 31;
        float2 acc = make_float2(0.f, 0.f);
#pragma unroll
        for (int s = 0; s < S_; s++) {
            float m = mulp[k][s];
            float2 x = *reinterpret_cast<const float2*>(&xu[s][2 * d2]);
            acc.x = fmaf(m, x.x, acc.x);
            acc.y = fmaf(m, x.y, acc.y);
        }
        *reinterpret_cast<float2*>(&delta[k][2 * d2]) = acc;
    }
    for (int i = tid; i < S_ * 16; i += 256) {
        int s = i >> 4, q = i & 15;
        float4 p = *reinterpret_cast<const float4*>(&Pktb[s][0]);
        float4 c0 = reinterpret_cast<const float4*>(&Cu[0][0])[q];
        float4 c1 = reinterpret_cast<const float4*>(&Cu[1][0])[q];
        float4 c2 = reinterpret_cast<const float4*>(&Cu[2][0])[q];
        float4 c3 = reinterpret_cast<const float4*>(&Cu[3][0])[q];
        float4 r;
        r.x = p.x*c0.x + p.y*c1.x + p.z*c2.x + p.w*c3.x;
        r.y = p.x*c0.y + p.y*c1.y + p.z*c2.y + p.w*c3.y;
        r.z = p.x*c0.z + p.y*c1.z + p.z*c2.z + p.w*c3.z;
        r.w = p.x*c0.w + p.y*c1.w + p.z*c2.w + p.w*c3.w;
        reinterpret_cast<float4*>(&buf2[s][0])[q] = r;
    }
    __syncthreads();

    if (w < K_) {
        int k = w;
        float d0 = delta[k][lane], d1 = delta[k][lane + 32];
        float n = warpsum(d0 * d0 + d1 * d1);
        if (lane == 0) nrm2[k] = 1.f / fmaxf(sqrtf(n), 1e-12f);
    }
    __syncthreads();
    {
        int k = tid >> 6, d = tid & 63;
        delta[k][d] *= nrm2[k];
    }
    __syncthreads();

    {
        const float2* w3v = reinterpret_cast<const float2*>(w3);
        const float w4a = __ldg(&w4[2 * lane]);
        const float w4b = __ldg(&w4[2 * lane + 1]);
        float a0[7], a1[7];
#pragma unroll
        for (int c = 0; c < 7; c++) { a0[c] = 0.f; a1[c] = 0.f; }
        for (int d = 0; d < D_; d++) {
            float2 wv = __ldg(&w3v[d * 32 + lane]);
#pragma unroll
            for (int c = 0; c < 7; c++) {
                int s = w + 8 * c;
                if (s < S_) {
                    float xv = buf2[s][d];
                    a0[c] = fmaf(xv, wv.x, a0[c]);
                    a1[c] = fmaf(xv, wv.y, a1[c]);
                }
            }
        }
#pragma unroll
        for (int c = 0; c < 7; c++) {
            int s = w + 8 * c;
            if (s < S_) {
                float t = tanhf(a0[c]) * w4a + tanhf(a1[c]) * w4b;
                t = warpsum(t);
                if (lane == 0) logit[s] = t;
            }
        }
    }
    __syncthreads();
    if (w == 0) {
        float v0 = (lane < S_) ? logit[lane] : -1e30f;
        float v1 = (lane + 32 < S_) ? logit[lane + 32] : -1e30f;
        float m = warpmax(fmaxf(v0, v1));
        float e0 = (lane < S_) ? expf(v0 - m) : 0.f;
        float e1 = (lane + 32 < S_) ? expf(v1 - m) : 0.f;
        float inv = 1.f / warpsum(e0 + e1);
        if (lane < S_) aw[lane] = e0 * inv;
        if (lane + 32 < S_) aw[lane + 32] = e1 * inv;
    }
    __syncthreads();
    if (tid < D_) {
        float acc = 0.f;
#pragma unroll
        for (int s = 0; s < S_; s++) acc = fmaf(aw[s], buf2[s][tid], acc);
        capt[tid] = acc;
    }
    __syncthreads();
    if (w == 0) {
        float c0 = capt[lane], c1 = capt[lane + 32];
        float mean = warpsum(c0 + c1) * (1.f / 64.f);
        float d0 = c0 - mean, d1 = c1 - mean;
        float var = warpsum(d0 * d0 + d1 * d1) * (1.f / 64.f);
        float inv = rsqrtf(var + LN_EPS);
        capt[lane]      = d0 * inv * __ldg(&ln4w[lane])      + __ldg(&ln4b[lane]);
        capt[lane + 32] = d1 * inv * __ldg(&ln4w[lane + 32]) + __ldg(&ln4b[lane + 32]);
    }
    __syncthreads();

    if (w < K_) {
        int k = w;
        float p = delta[k][lane] * capt[lane] + delta[k][lane + 32] * capt[lane + 32];
        p = warpsum(p) * (1.f / TAU_);
        if (lane == 0) ekw[k] = p;
    }
    __syncthreads();
    if (tid == 0) {
        float m = fmaxf(fmaxf(ekw[0], ekw[1]), fmaxf(ekw[2], ekw[3]));
        float e0 = expf(ekw[0] - m), e1 = expf(ekw[1] - m);
        float e2 = expf(ekw[2] - m), e3 = expf(ekw[3] - m);
        float inv = 1.f / (e0 + e1 + e2 + e3);
        ekw[0] = e0 * inv; ekw[1] = e1 * inv; ekw[2] = e2 * inv; ekw[3] = e3 * inv;
    }
    __syncthreads();
    if (tid < D_) {
        vstage[tid] = ekw[0] * delta[0][tid] + ekw[1] * delta[1][tid]
                    + ekw[2] * delta[2][tid] + ekw[3] * delta[3][tid];
    }
    __syncthreads();
    if (tid < 32) {
        int j = tid;
        float v0 = vstage[2 * j], v1 = vstage[2 * j + 1];
        __nv_bfloat16 h0 = __float2bfloat16(v0), h1 = __float2bfloat16(v1);
        uint32_t hw = pack_bf16(v0, v1);
        uint32_t lw = pack_bf16(v0 - __bfloat162float(h0), v1 - __bfloat162float(h1));
        int rt = b >> 4, rr = b & 15;
        int role = rr >> 3, lg2 = rr & 7;
        int kk = j >> 3, t = j & 7, q2 = t & 3, h8 = t >> 2;
        int lane2 = lg2 * 4 + q2;
        int slot = role + 2 * h8;
        int frag = (rt * 4 + kk) * 32 + lane2;
        reinterpret_cast<uint32_t*>(&g_vufh[frag])[slot] = hw;
        reinterpret_cast<uint32_t*>(&g_vufl[frag])[slot] = lw;
    }
}

// ---------------------------------------------------------------------------
// Kernel 4: scores — M-resident A (registers, loaded once), N-streaming B.
// grid (49, 16), 256 thr. Each warp owns one 16-row A tile of its M-block.
// ---------------------------------------------------------------------------
#define BSTR2 72
#define NTILES 782          // ceil(100000 / 128)
#define GX 49
__global__ __launch_bounds__(256) void scores_mres(
    const float* __restrict__ item_emb,
    float* __restrict__ out)
{
    __shared__ __align__(16) __nv_bfloat16 bh[128 * BSTR2];
    __shared__ __align__(16) __nv_bfloat16 bl[128 * BSTR2];

    const int tid = threadIdx.x, lane = tid & 31, w = tid >> 5;
    const int rt = blockIdx.y * 8 + w;     // 16-row fragment tile, 0..127

    // A fragments: loaded ONCE
    uint4 Afh[4], Afl[4];
#pragma unroll
    for (int kk = 0; kk < 4; kk++) {
        Afh[kk] = g_vufh[(rt * 4 + kk) * 32 + lane];
        Afl[kk] = g_vufl[(rt * 4 + kk) * 32 + lane];
    }

    const int lg = lane >> 2, q = lane & 3;
    const int rig = lane & 7, mcode = lane >> 3;
    const int j_off = mcode >> 1, khalf = mcode & 1;
    uint32_t bhb = (uint32_t)__cvta_generic_to_shared(bh)
                 + ((j_off * 8 + rig) * BSTR2 + khalf * 8) * 2;
    uint32_t blb = (uint32_t)__cvta_generic_to_shared(bl)
                 + ((j_off * 8 + rig) * BSTR2 + khalf * 8) * 2;

    const int r0base = rt * 16 + lg;       // global row of acc[..][0..1]
    float* orow0 = out + (size_t)r0base * N_;
    float* orow1 = out + (size_t)(r0base + 8) * N_;

    // staged tile (registers)
    float4 st[8];
    int nt = blockIdx.x;
    {
        int nb = nt * 128;
#pragma unroll
        for (int i = 0; i < 8; i++) {
            int idx = tid + i * 256;
            int row = idx >> 4, q4 = idx & 15;
            int ng = nb + row;
            st[i] = (ng < N_)
                ? __ldg(&reinterpret_cast<const float4*>(item_emb + (size_t)ng * D_)[q4])
                : make_float4(0.f, 0.f, 0.f, 0.f);
        }
    }

    for (; nt < NTILES; nt += GX) {
        // convert staged tile -> smem hi/lo
#pragma unroll
        for (int i = 0; i < 8; i++) {
            int idx = tid + i * 256;
            int row = idx >> 4, q4 = idx & 15;
            float4 v = st[i];
            uint32_t h0 = pack_bf16(v.x, v.y), h1 = pack_bf16(v.z, v.w);
            __nv_bfloat162 b0 = *reinterpret_cast<__nv_bfloat162*>(&h0);
            __nv_bfloat162 b1 = *reinterpret_cast<__nv_bfloat162*>(&h1);
            uint32_t l0 = pack_bf16(v.x - __bfloat162float(b0.x), v.y - __bfloat162float(b0.y));
            uint32_t l1 = pack_bf16(v.z - __bfloat162float(b1.x), v.w - __bfloat162float(b1.y));
            *reinterpret_cast<uint2*>(&bh[row * BSTR2 + q4 * 4]) = make_uint2(h0, h1);
            *reinterpret_cast<uint2*>(&bl[row * BSTR2 + q4 * 4]) = make_uint2(l0, l1);
        }
        __syncthreads();

        // prefetch next tile (LDGs issued, consumed after compute)
        int ntn = nt + GX;
        if (ntn < NTILES) {
            int nb = ntn * 128;
#pragma unroll
            for (int i = 0; i < 8; i++) {
                int idx = tid + i * 256;
                int row = idx >> 4, q4 = idx & 15;
                int ng = nb + row;
                st[i] = (ng < N_)
                    ? __ldg(&reinterpret_cast<const float4*>(item_emb + (size_t)ng * D_)[q4])
                    : make_float4(0.f, 0.f, 0.f, 0.f);
            }
        }

        // compute 16(M) x 128(N)
        float acc[16][4];
#pragma unroll
        for (int j = 0; j < 16; j++) {
            acc[j][0]=0.f; acc[j][1]=0.f; acc[j][2]=0.f; acc[j][3]=0.f;
        }
#pragma unroll
        for (int kk = 0; kk < 4; kk++) {
#pragma unroll
            for (int p = 0; p < 8; p++) {
                uint32_t b0h,b1h,b2h,b3h, b0l,b1l,b2l,b3l;
                uint32_t off = (uint32_t)(p * 16 * BSTR2 * 2 + kk * 32);
                LDSM4(b0h,b1h,b2h,b3h, bhb + off);
                LDSM4(b0l,b1l,b2l,b3l, blb + off);
                int j0 = 2 * p, j1 = 2 * p + 1;
                MMA_BF16(acc[j0][0],acc[j0][1],acc[j0][2],acc[j0][3],
                         Afh[kk].x,Afh[kk].y,Afh[kk].z,Afh[kk].w, b0h,b1h);
                MMA_BF16(acc[j0][0],acc[j0][1],acc[j0][2],acc[j0][3],
                         Afh[kk].x,Afh[kk].y,Afh[kk].z,Afh[kk].w, b0l,b1l);
                MMA_BF16(acc[j0][0],acc[j0][1],acc[j0][2],acc[j0][3],
                         Afl[kk].x,Afl[kk].y,Afl[kk].z,Afl[kk].w, b0h,b1h);
                MMA_BF16(acc[j1][0],acc[j1][1],acc[j1][2],acc[j1][3],
                         Afh[kk].x,Afh[kk].y,Afh[kk].z,Afh[kk].w, b2h,b3h);
                MMA_BF16(acc[j1][0],acc[j1][1],acc[j1][2],acc[j1][3],
                         Afh[kk].x,Afh[kk].y,Afh[kk].z,Afh[kk].w, b2l,b3l);
                MMA_BF16(acc[j1][0],acc[j1][1],acc[j1][2],acc[j1][3],
                         Afl[kk].x,Afl[kk].y,Afl[kk].z,Afl[kk].w, b2h,b3h);
            }
        }

        // stores
        const int nbase = nt * 128;
#pragma unroll
        for (int j = 0; j < 16; j++) {
            int n0 = nbase + j * 8 + 2 * q;
            if (n0 < N_) {
                __stcs(reinterpret_cast<float2*>(orow0 + n0),
                       make_float2(acc[j][0], acc[j][1]));
                __stcs(reinterpret_cast<float2*>(orow1 + n0),
                       make_float2(acc[j][2], acc[j][3]));
            }
        }
        __syncthreads();   // protect bh/bl before next overwrite
    }
}

extern "C" void kernel_launch(void* const* d_in, const int* in_sizes, int n_in,
                              void* d_out, int out_size) {
    const int* item_seq = (const int*)d_in[0];
    const float* item_emb = (const float*)d_in[2];
    const float* Cg  = (const float*)d_in[3];
    const float* w1  = (const float*)d_in[4];
    const float* w2  = (const float*)d_in[5];
    const float* w3  = (const float*)d_in[6];
    const float* w4  = (const float*)d_in[7];
    const float* wk1 = (const float*)d_in[8];
    const float* wk2 = (const float*)d_in[9];
    const float* ln2w = (const float*)d_in[10];
    const float* ln2b = (const float*)d_in[11];
    const float* ln4w = (const float*)d_in[12];
    const float* ln4b = (const float*)d_in[13];
    float* out = (float*)d_out;

    rowgemm_kernel<<<ROWS_ / 128, 256>>>(item_seq, item_emb, wk1, wk2, w1, w2, w3);
    zu_kernel<<<B_, 64>>>(item_seq, item_emb);
    su_kernel<<<B_ / 16, 256>>>(Cg);
    head_kernel<<<B_, 256>>>(item_seq, item_emb, Cg, w3, w4,
                             ln2w, ln2b, ln4w, ln4b);
    dim3 sg(GX, 16);
    scores_mres<<<sg, 256>>>(item_emb, out);
}

// round 14
// speedup vs baseline: 1.1916x; 1.1916x over previous
#include <cuda_runtime.h>
#include <cuda_bf16.h>
#include <cstdint>

#define B_ 2048
#define S_ 50
#define D_ 64
#define L_ 500
#define K_ 4
#define N_ 100000
#define TAU_ 0.1f
#define LN_EPS 1e-12f
#define ROWS_ (B_ * S_)

// v_u in MMA-fragment order (hi/lo): [rowtile 128][kk 4][lane 32] each uint4
__device__ uint4 g_vufh[128 * 4 * 32];
__device__ uint4 g_vufl[128 * 4 * 32];
// rowgemm outputs
__device__ float g_aklog[K_ * ROWS_];
__device__ float g_logit[ROWS_];
__device__ float g_w3n[ROWS_ * D_];
// zu / su
__device__ float g_zu[B_ * D_];
__device__ float g_su[B_ * L_];

__device__ __forceinline__ float warpsum(float v) {
#pragma unroll
    for (int o = 16; o; o >>= 1) v += __shfl_xor_sync(0xffffffffu, v, o);
    return v;
}
__device__ __forceinline__ float warpmax(float v) {
#pragma unroll
    for (int o = 16; o; o >>= 1) v = fmaxf(v, __shfl_xor_sync(0xffffffffu, v, o));
    return v;
}
__device__ __forceinline__ uint32_t pack_bf16(float a, float b) {
    __nv_bfloat162 t = __floats2bfloat162_rn(a, b);
    return *reinterpret_cast<uint32_t*>(&t);
}

#define MMA_BF16(d0,d1,d2,d3,a0,a1,a2,a3,b0,b1)                              \
    asm volatile("mma.sync.aligned.m16n8k16.row.col.f32.bf16.bf16.f32 "      \
        "{%0,%1,%2,%3}, {%4,%5,%6,%7}, {%8,%9}, {%0,%1,%2,%3};"              \
        : "+f"(d0), "+f"(d1), "+f"(d2), "+f"(d3)                             \
        : "r"(a0), "r"(a1), "r"(a2), "r"(a3), "r"(b0), "r"(b1))
#define LDSM4(r0,r1,r2,r3,addr)                                              \
    asm volatile("ldmatrix.sync.aligned.m8n8.x4.shared.b16 {%0,%1,%2,%3}, [%4];" \
        : "=r"(r0), "=r"(r1), "=r"(r2), "=r"(r3) : "r"(addr))

// ---------------------------------------------------------------------------
// Kernel 0: rowgemm (unchanged)
// ---------------------------------------------------------------------------
#define ASTR 72
__global__ __launch_bounds__(256) void rowgemm_kernel(
    const int* __restrict__ item_seq, const float* __restrict__ item_emb,
    const float* __restrict__ wk1, const float* __restrict__ wk2,
    const float* __restrict__ w1, const float* __restrict__ w2,
    const float* __restrict__ w3)
{
    __shared__ __align__(16) __nv_bfloat16 Ah[128 * ASTR];
    __shared__ __align__(16) __nv_bfloat16 Al[128 * ASTR];
    __shared__ __align__(16) __nv_bfloat16 Bh[D_ * ASTR];
    __shared__ __align__(16) __nv_bfloat16 Bl[D_ * ASTR];
    __shared__ float wvec[D_];

    const int tid = threadIdx.x, lane = tid & 31, w = tid >> 5;
    const int rbase = blockIdx.x * 128;
    {
        int r = tid >> 1, h = tid & 1;
        int it = __ldg(&item_seq[rbase + r]);
        const float4* ep = reinterpret_cast<const float4*>(item_emb + (size_t)it * D_) + h * 8;
        uint32_t* dh = reinterpret_cast<uint32_t*>(Ah + r * ASTR + h * 32);
        uint32_t* dl = reinterpret_cast<uint32_t*>(Al + r * ASTR + h * 32);
#pragma unroll
        for (int i = 0; i < 8; i++) {
            float4 f = __ldg(&ep[i]);
            uint32_t h0 = pack_bf16(f.x, f.y), h1 = pack_bf16(f.z, f.w);
            __nv_bfloat162 b0 = *reinterpret_cast<__nv_bfloat162*>(&h0);
            __nv_bfloat162 b1 = *reinterpret_cast<__nv_bfloat162*>(&h1);
            dh[2*i] = h0; dh[2*i+1] = h1;
            dl[2*i]   = pack_bf16(f.x - __bfloat162float(b0.x), f.y - __bfloat162float(b0.y));
            dl[2*i+1] = pack_bf16(f.z - __bfloat162float(b1.x), f.w - __bfloat162float(b1.y));
        }
    }
    const int lg = lane >> 2, q = lane & 3;
    const int rig = lane & 7, mcode = lane >> 3;
    const int j_off = mcode >> 1, khalf = mcode & 1;
    const int mbase = w * 16;
    uint32_t aBh = (uint32_t)__cvta_generic_to_shared(Ah)
                 + ((mbase + (lane & 7) + ((lane >> 3) & 1) * 8) * ASTR + ((lane >> 4) * 8)) * 2;
    uint32_t aBl = (uint32_t)__cvta_generic_to_shared(Al)
                 + ((mbase + (lane & 7) + ((lane >> 3) & 1) * 8) * ASTR + ((lane >> 4) * 8)) * 2;
    uint32_t bBh = (uint32_t)__cvta_generic_to_shared(Bh)
                 + ((j_off * 8 + rig) * ASTR + khalf * 8) * 2;
    uint32_t bBl = (uint32_t)__cvta_generic_to_shared(Bl)
                 + ((j_off * 8 + rig) * ASTR + khalf * 8) * 2;
    const int r0g = rbase + mbase + lg, r1g = r0g + 8;

    for (int widx = 0; widx < 6; widx++) {
        __syncthreads();
        const float* W = (widx < 4) ? (wk1 + widx * D_ * D_) : (widx == 4 ? w1 : w3);
        const float4* Wv = reinterpret_cast<const float4*>(W);
#pragma unroll
        for (int i = 0; i < 4; i++) {
            int f = tid + i * 256;
            float4 v = __ldg(&Wv[f]);
            int d = f >> 4, e0 = (f & 15) * 4;
            const float* vv = &v.x;
#pragma unroll
            for (int j = 0; j < 4; j++) {
                float val = vv[j];
                __nv_bfloat16 h = __float2bfloat16(val);
                Bh[(e0 + j) * ASTR + d] = h;
                Bl[(e0 + j) * ASTR + d] = __float2bfloat16(val - __bfloat162float(h));
            }
        }
        if (tid < D_) {
            if (widx < 4)       wvec[tid] = __ldg(&wk2[widx * D_ + tid]);
            else if (widx == 4) wvec[tid] = __ldg(&w2[tid]);
        }
        __syncthreads();

        float acc[8][4];
#pragma unroll
        for (int j = 0; j < 8; j++) { acc[j][0]=0.f; acc[j][1]=0.f; acc[j][2]=0.f; acc[j][3]=0.f; }
#pragma unroll
        for (int kk = 0; kk < 4; kk++) {
            uint32_t ah0,ah1,ah2,ah3, al0,al1,al2,al3;
            LDSM4(ah0,ah1,ah2,ah3, aBh + kk * 32);
            LDSM4(al0,al1,al2,al3, aBl + kk * 32);
#pragma unroll
            for (int p = 0; p < 4; p++) {
                uint32_t b0h,b1h,b2h,b3h, b0l,b1l,b2l,b3l;
                uint32_t off = (uint32_t)(p * 16 * ASTR * 2 + kk * 32);
                LDSM4(b0h,b1h,b2h,b3h, bBh + off);
                LDSM4(b0l,b1l,b2l,b3l, bBl + off);
                int j0 = 2 * p, j1 = 2 * p + 1;
                MMA_BF16(acc[j0][0],acc[j0][1],acc[j0][2],acc[j0][3], ah0,ah1,ah2,ah3, b0h,b1h);
                MMA_BF16(acc[j0][0],acc[j0][1],acc[j0][2],acc[j0][3], ah0,ah1,ah2,ah3, b0l,b1l);
                MMA_BF16(acc[j0][0],acc[j0][1],acc[j0][2],acc[j0][3], al0,al1,al2,al3, b0h,b1h);
                MMA_BF16(acc[j1][0],acc[j1][1],acc[j1][2],acc[j1][3], ah0,ah1,ah2,ah3, b2h,b3h);
                MMA_BF16(acc[j1][0],acc[j1][1],acc[j1][2],acc[j1][3], ah0,ah1,ah2,ah3, b2l,b3l);
                MMA_BF16(acc[j1][0],acc[j1][1],acc[j1][2],acc[j1][3], al0,al1,al2,al3, b2h,b3h);
            }
        }
        if (widx < 5) {
            float s0 = 0.f, s1 = 0.f;
#pragma unroll
            for (int j = 0; j < 8; j++) {
                int e0 = j * 8 + 2 * q;
                float w0 = wvec[e0], w1v = wvec[e0 + 1];
                s0 += tanhf(acc[j][0]) * w0 + tanhf(acc[j][1]) * w1v;
                s1 += tanhf(acc[j][2]) * w0 + tanhf(acc[j][3]) * w1v;
            }
            s0 += __shfl_xor_sync(0xffffffffu, s0, 1);
            s0 += __shfl_xor_sync(0xffffffffu, s0, 2);
            s1 += __shfl_xor_sync(0xffffffffu, s1, 1);
            s1 += __shfl_xor_sync(0xffffffffu, s1, 2);
            if (q == 0) {
                if (widx < 4) { g_aklog[widx * ROWS_ + r0g] = s0; g_aklog[widx * ROWS_ + r1g] = s1; }
                else          { g_logit[r0g] = s0; g_logit[r1g] = s1; }
            }
        } else {
            float n0 = 0.f, n1 = 0.f;
#pragma unroll
            for (int j = 0; j < 8; j++) {
                n0 += acc[j][0]*acc[j][0] + acc[j][1]*acc[j][1];
                n1 += acc[j][2]*acc[j][2] + acc[j][3]*acc[j][3];
            }
            n0 += __shfl_xor_sync(0xffffffffu, n0, 1);
            n0 += __shfl_xor_sync(0xffffffffu, n0, 2);
            n1 += __shfl_xor_sync(0xffffffffu, n1, 1);
            n1 += __shfl_xor_sync(0xffffffffu, n1, 2);
            float inv0 = 1.f / fmaxf(sqrtf(n0), 1e-12f);
            float inv1 = 1.f / fmaxf(sqrtf(n1), 1e-12f);
#pragma unroll
            for (int j = 0; j < 8; j++) {
                int c0 = j * 8 + 2 * q;
                *reinterpret_cast<float2*>(g_w3n + (size_t)r0g * D_ + c0) =
                    make_float2(acc[j][0] * inv0, acc[j][1] * inv0);
                *reinterpret_cast<float2*>(g_w3n + (size_t)r1g * D_ + c0) =
                    make_float2(acc[j][2] * inv1, acc[j][3] * inv1);
            }
        }
    }
}

// ---------------------------------------------------------------------------
// Kernel 1: zu (unchanged)
// ---------------------------------------------------------------------------
__global__ __launch_bounds__(64) void zu_kernel(
    const int* __restrict__ item_seq, const float* __restrict__ item_emb)
{
    __shared__ float aw[S_];
    __shared__ int   seqs[S_];
    __shared__ __align__(16) float4 part[4][16];
    const int b = blockIdx.x, tid = threadIdx.x;
    if (tid < S_) seqs[tid] = __ldg(&item_seq[b * S_ + tid]);
    if (tid < 32) {
        const float* lp = g_logit + b * S_;
        float v0 = (tid < S_) ? lp[tid] : -1e30f;
        float v1 = (tid + 32 < S_) ? lp[tid + 32] : -1e30f;
        float m = warpmax(fmaxf(v0, v1));
        float e0 = (tid < S_) ? expf(v0 - m) : 0.f;
        float e1 = (tid + 32 < S_) ? expf(v1 - m) : 0.f;
        float inv = 1.f / warpsum(e0 + e1);
        if (tid < S_) aw[tid] = e0 * inv;
        if (tid + 32 < S_) aw[tid + 32] = e1 * inv;
    }
    __syncthreads();
    int qd = tid & 15, strip = tid >> 4;
    float4 acc = make_float4(0.f, 0.f, 0.f, 0.f);
    for (int s = strip; s < S_; s += 4) {
        const float4* xp = reinterpret_cast<const float4*>(item_emb + (size_t)seqs[s] * D_);
        float4 x = __ldg(&xp[qd]);
        float a = aw[s];
        acc.x = fmaf(a, x.x, acc.x); acc.y = fmaf(a, x.y, acc.y);
        acc.z = fmaf(a, x.z, acc.z); acc.w = fmaf(a, x.w, acc.w);
    }
    part[strip][qd] = acc;
    __syncthreads();
    if (tid < 16) {
        float4 a = part[0][tid], b1 = part[1][tid], c = part[2][tid], d = part[3][tid];
        reinterpret_cast<float4*>(g_zu + b * D_)[tid] =
            make_float4(a.x+b1.x+c.x+d.x, a.y+b1.y+c.y+d.y, a.z+b1.z+c.z+d.z, a.w+b1.w+c.w+d.w);
    }
}

// ---------------------------------------------------------------------------
// Kernel 2: su (unchanged)
// ---------------------------------------------------------------------------
__global__ __launch_bounds__(256) void su_kernel(const float* __restrict__ Cg)
{
    __shared__ __align__(16) float Zs[16][D_];
    const int tid = threadIdx.x, bbase = blockIdx.x * 16;
    for (int i = tid; i < 16 * 16; i += 256) {
        int j = i >> 4, q = i & 15;
        reinterpret_cast<float4*>(&Zs[j][0])[q] =
            reinterpret_cast<const float4*>(g_zu + (bbase + j) * D_)[q];
    }
    __syncthreads();
    for (int l = tid; l < L_; l += 256) {
        float acc[16];
#pragma unroll
        for (int j = 0; j < 16; j++) acc[j] = 0.f;
        const float4* cr = reinterpret_cast<const float4*>(Cg + l * D_);
#pragma unroll
        for (int dq = 0; dq < 16; dq++) {
            float4 c = __ldg(&cr[dq]);
#pragma unroll
            for (int j = 0; j < 16; j++) {
                acc[j] = fmaf(c.x, Zs[j][4*dq],   acc[j]);
                acc[j] = fmaf(c.y, Zs[j][4*dq+1], acc[j]);
                acc[j] = fmaf(c.z, Zs[j][4*dq+2], acc[j]);
                acc[j] = fmaf(c.w, Zs[j][4*dq+3], acc[j]);
            }
        }
#pragma unroll
        for (int j = 0; j < 16; j++) g_su[(bbase + j) * L_ + l] = acc[j];
    }
}

// ---------------------------------------------------------------------------
// Kernel 3: head (unchanged)
// ---------------------------------------------------------------------------
__global__ __launch_bounds__(256) void head_kernel(
    const int* __restrict__ item_seq, const float* __restrict__ item_emb,
    const float* __restrict__ Cg,
    const float* __restrict__ w3, const float* __restrict__ w4,
    const float* __restrict__ ln2w, const float* __restrict__ ln2b,
    const float* __restrict__ ln4w, const float* __restrict__ ln4b)
{
    __shared__ __align__(16) float xu[S_][D_];
    __shared__ __align__(16) float buf2[S_][D_];
    __shared__ int   seqs[S_];
    __shared__ float logit[S_];
    __shared__ float aw[S_];
    __shared__ __align__(16) float su[L_];
    __shared__ float selv[K_];
    __shared__ int   seli[K_];
    __shared__ float stopv[K_];
    __shared__ int   sidx[K_];
    __shared__ __align__(16) float Cu[K_][D_];
    __shared__ __align__(16) float Cun[K_][D_];
    __shared__ __align__(16) float Pktb[S_][K_];
    __shared__ float mulp[K_][S_];
    __shared__ __align__(16) float delta[K_][D_];
    __shared__ float nrm2[K_];
    __shared__ float capt[D_];
    __shared__ float ekw[K_];
    __shared__ float vstage[D_];

    const int b = blockIdx.x, tid = threadIdx.x, lane = tid & 31, w = tid >> 5;

    if (tid < S_) seqs[tid] = __ldg(&item_seq[b * S_ + tid]);
    if (tid < 125)
        reinterpret_cast<float4*>(su)[tid] =
            __ldg(&reinterpret_cast<const float4*>(g_su + b * L_)[tid]);
    __syncthreads();
    {
        for (int i = tid; i < S_ * 16; i += 256) {
            int s = i >> 4, q = i & 15;
            const float4* ep = reinterpret_cast<const float4*>(item_emb + (size_t)seqs[s] * D_);
            reinterpret_cast<float4*>(&xu[s][0])[q] = __ldg(&ep[q]);
        }
        const float4* wp = reinterpret_cast<const float4*>(g_w3n + (size_t)b * S_ * D_);
        for (int i = tid; i < S_ * 16; i += 256) {
            int s = i >> 4, q = i & 15;
            reinterpret_cast<float4*>(&buf2[s][0])[q] = __ldg(&wp[i]);
        }
    }
    __syncthreads();

    if (w == 0) {
        for (int r = 0; r < K_; r++) {
            float mv = -1e30f; int mi = -1;
            for (int l = lane; l < L_; l += 32) {
                bool skip = false;
#pragma unroll
                for (int t = 0; t < K_; t++)
                    if (t < r && seli[t] == l) skip = true;
                float v = su[l];
                if (!skip && (v > mv || (v == mv && l > mi))) { mv = v; mi = l; }
            }
#pragma unroll
            for (int o = 16; o; o >>= 1) {
                float ov = __shfl_xor_sync(0xffffffffu, mv, o);
                int   oi = __shfl_xor_sync(0xffffffffu, mi, o);
                if (ov > mv || (ov == mv && oi > mi)) { mv = ov; mi = oi; }
            }
            if (lane == 0) { seli[r] = mi; selv[r] = mv; }
            __syncwarp();
        }
        if (lane < K_) { sidx[lane] = seli[K_ - 1 - lane]; stopv[lane] = selv[K_ - 1 - lane]; }
    }
    __syncthreads();

    if (w < K_) {
        int k = w;
        float sg = 1.f / (1.f + expf(-stopv[k]));
        const float* cr = Cg + sidx[k] * D_;
        float v0 = __ldg(&cr[lane]) * sg;
        float v1 = __ldg(&cr[lane + 32]) * sg;
        Cu[k][lane] = v0; Cu[k][lane + 32] = v1;
        float mean = warpsum(v0 + v1) * (1.f / 64.f);
        float d0 = v0 - mean, d1 = v1 - mean;
        float var = warpsum(d0 * d0 + d1 * d1) * (1.f / 64.f);
        float inv = rsqrtf(var + LN_EPS);
        Cun[k][lane]      = d0 * inv * __ldg(&ln2w[lane])      + __ldg(&ln2b[lane]);
        Cun[k][lane + 32] = d1 * inv * __ldg(&ln2w[lane + 32]) + __ldg(&ln2b[lane + 32]);
    }
    __syncthreads();

    if (tid < S_ * K_) {
        int s = tid >> 2, k = tid & 3;
        const float4* bp = reinterpret_cast<const float4*>(&buf2[s][0]);
        const float4* cp = reinterpret_cast<const float4*>(&Cun[k][0]);
        float acc = 0.f;
#pragma unroll
        for (int q = 0; q < 16; q++) {
            float4 x = bp[q], c = cp[q];
            acc += x.x*c.x + x.y*c.y + x.z*c.z + x.w*c.w;
        }
        Pktb[s][k] = acc;
    }
    __syncthreads();
    if (tid < S_) {
        float v0 = Pktb[tid][0], v1 = Pktb[tid][1], v2 = Pktb[tid][2], v3 = Pktb[tid][3];
        float m = fmaxf(fmaxf(v0, v1), fmaxf(v2, v3));
        float e0 = expf(v0 - m), e1 = expf(v1 - m), e2 = expf(v2 - m), e3 = expf(v3 - m);
        float inv = 1.f / (e0 + e1 + e2 + e3);
        Pktb[tid][0] = e0 * inv; Pktb[tid][1] = e1 * inv;
        Pktb[tid][2] = e2 * inv; Pktb[tid][3] = e3 * inv;
    }
    __syncthreads();

    if (w < K_) {
        int k = w;
        const float* akr = g_aklog + k * ROWS_ + b * S_;
        float v0 = (lane < S_) ? akr[lane] : -1e30f;
        float v1 = (lane + 32 < S_) ? akr[lane + 32] : -1e30f;
        float m = warpmax(fmaxf(v0, v1));
        float e0 = (lane < S_) ? expf(v0 - m) : 0.f;
        float e1 = (lane + 32 < S_) ? expf(v1 - m) : 0.f;
        float inv = 1.f / warpsum(e0 + e1);
        if (lane < S_) mulp[k][lane] = Pktb[lane][k] * e0 * inv;
        if (lane + 32 < S_) mulp[k][lane + 32] = Pktb[lane + 32][k] * e1 * inv;
    }
    __syncthreads();

    if (tid < 128) {
        int k = tid >> 5, d2 = tid & 31;
        float2 acc = make_float2(0.f, 0.f);
#pragma unroll
        for (int s = 0; s < S_; s++) {
            float m = mulp[k][s];
            float2 x = *reinterpret_cast<const float2*>(&xu[s][2 * d2]);
            acc.x = fmaf(m, x.x, acc.x);
            acc.y = fmaf(m, x.y, acc.y);
        }
        *reinterpret_cast<float2*>(&delta[k][2 * d2]) = acc;
    }
    for (int i = tid; i < S_ * 16; i += 256) {
        int s = i >> 4, q = i & 15;
        float4 p = *reinterpret_cast<const float4*>(&Pktb[s][0]);
        float4 c0 = reinterpret_cast<const float4*>(&Cu[0][0])[q];
        float4 c1 = reinterpret_cast<const float4*>(&Cu[1][0])[q];
        float4 c2 = reinterpret_cast<const float4*>(&Cu[2][0])[q];
        float4 c3 = reinterpret_cast<const float4*>(&Cu[3][0])[q];
        float4 r;
        r.x = p.x*c0.x + p.y*c1.x + p.z*c2.x + p.w*c3.x;
        r.y = p.x*c0.y + p.y*c1.y + p.z*c2.y + p.w*c3.y;
        r.z = p.x*c0.z + p.y*c1.z + p.z*c2.z + p.w*c3.z;
        r.w = p.x*c0.w + p.y*c1.w + p.z*c2.w + p.w*c3.w;
        reinterpret_cast<float4*>(&buf2[s][0])[q] = r;
    }
    __syncthreads();

    if (w < K_) {
        int k = w;
        float d0 = delta[k][lane], d1 = delta[k][lane + 32];
        float n = warpsum(d0 * d0 + d1 * d1);
        if (lane == 0) nrm2[k] = 1.f / fmaxf(sqrtf(n), 1e-12f);
    }
    __syncthreads();
    {
        int k = tid >> 6, d = tid & 63;
        delta[k][d] *= nrm2[k];
    }
    __syncthreads();

    {
        const float2* w3v = reinterpret_cast<const float2*>(w3);
        const float w4a = __ldg(&w4[2 * lane]);
        const float w4b = __ldg(&w4[2 * lane + 1]);
        float a0[7], a1[7];
#pragma unroll
        for (int c = 0; c < 7; c++) { a0[c] = 0.f; a1[c] = 0.f; }
        for (int d = 0; d < D_; d++) {
            float2 wv = __ldg(&w3v[d * 32 + lane]);
#pragma unroll
            for (int c = 0; c < 7; c++) {
                int s = w + 8 * c;
                if (s < S_) {
                    float xv = buf2[s][d];
                    a0[c] = fmaf(xv, wv.x, a0[c]);
                    a1[c] = fmaf(xv, wv.y, a1[c]);
                }
            }
        }
#pragma unroll
        for (int c = 0; c < 7; c++) {
            int s = w + 8 * c;
            if (s < S_) {
                float t = tanhf(a0[c]) * w4a + tanhf(a1[c]) * w4b;
                t = warpsum(t);
                if (lane == 0) logit[s] = t;
            }
        }
    }
    __syncthreads();
    if (w == 0) {
        float v0 = (lane < S_) ? logit[lane] : -1e30f;
        float v1 = (lane + 32 < S_) ? logit[lane + 32] : -1e30f;
        float m = warpmax(fmaxf(v0, v1));
        float e0 = (lane < S_) ? expf(v0 - m) : 0.f;
        float e1 = (lane + 32 < S_) ? expf(v1 - m) : 0.f;
        float inv = 1.f / warpsum(e0 + e1);
        if (lane < S_) aw[lane] = e0 * inv;
        if (lane + 32 < S_) aw[lane + 32] = e1 * inv;
    }
    __syncthreads();
    if (tid < D_) {
        float acc = 0.f;
#pragma unroll
        for (int s = 0; s < S_; s++) acc = fmaf(aw[s], buf2[s][tid], acc);
        capt[tid] = acc;
    }
    __syncthreads();
    if (w == 0) {
        float c0 = capt[lane], c1 = capt[lane + 32];
        float mean = warpsum(c0 + c1) * (1.f / 64.f);
        float d0 = c0 - mean, d1 = c1 - mean;
        float var = warpsum(d0 * d0 + d1 * d1) * (1.f / 64.f);
        float inv = rsqrtf(var + LN_EPS);
        capt[lane]      = d0 * inv * __ldg(&ln4w[lane])      + __ldg(&ln4b[lane]);
        capt[lane + 32] = d1 * inv * __ldg(&ln4w[lane + 32]) + __ldg(&ln4b[lane + 32]);
    }
    __syncthreads();

    if (w < K_) {
        int k = w;
        float p = delta[k][lane] * capt[lane] + delta[k][lane + 32] * capt[lane + 32];
        p = warpsum(p) * (1.f / TAU_);
        if (lane == 0) ekw[k] = p;
    }
    __syncthreads();
    if (tid == 0) {
        float m = fmaxf(fmaxf(ekw[0], ekw[1]), fmaxf(ekw[2], ekw[3]));
        float e0 = expf(ekw[0] - m), e1 = expf(ekw[1] - m);
        float e2 = expf(ekw[2] - m), e3 = expf(ekw[3] - m);
        float inv = 1.f / (e0 + e1 + e2 + e3);
        ekw[0] = e0 * inv; ekw[1] = e1 * inv; ekw[2] = e2 * inv; ekw[3] = e3 * inv;
    }
    __syncthreads();
    if (tid < D_) {
        vstage[tid] = ekw[0] * delta[0][tid] + ekw[1] * delta[1][tid]
                    + ekw[2] * delta[2][tid] + ekw[3] * delta[3][tid];
    }
    __syncthreads();
    if (tid < 32) {
        int j = tid;
        float v0 = vstage[2 * j], v1 = vstage[2 * j + 1];
        __nv_bfloat16 h0 = __float2bfloat16(v0), h1 = __float2bfloat16(v1);
        uint32_t hw = pack_bf16(v0, v1);
        uint32_t lw = pack_bf16(v0 - __bfloat162float(h0), v1 - __bfloat162float(h1));
        int rt = b >> 4, rr = b & 15;
        int role = rr >> 3, lg2 = rr & 7;
        int kk = j >> 3, t = j & 7, q2 = t & 3, h8 = t >> 2;
        int lane2 = lg2 * 4 + q2;
        int slot = role + 2 * h8;
        int frag = (rt * 4 + kk) * 32 + lane2;
        reinterpret_cast<uint32_t*>(&g_vufh[frag])[slot] = hw;
        reinterpret_cast<uint32_t*>(&g_vufl[frag])[slot] = lw;
    }
}

// ---------------------------------------------------------------------------
// Kernel 4: scores — register-resident B, 256 thr / 8 M-warps (1 rowtile per
// warp per mt), N=32 per CTA, MSPLIT=2. More warps/SM -> higher tensor duty.
// ---------------------------------------------------------------------------
#define BSTR2 72
#define MSPLIT 2
__global__ __launch_bounds__(256) void scores_frag(
    const float* __restrict__ item_emb,
    float* __restrict__ out)
{
    __shared__ __align__(16) __nv_bfloat16 bh[32 * BSTR2];
    __shared__ __align__(16) __nv_bfloat16 bl[32 * BSTR2];

    const int tid = threadIdx.x, lane = tid & 31, wm = tid >> 5;  // wm 0..7
    const int nbase = blockIdx.x * 32;

    // stage B tile [32 rows][64 k] hi/lo
    for (int i = tid; i < 512; i += 256) {
        int row = i >> 4, q4 = i & 15;
        float4 v = __ldg(&reinterpret_cast<const float4*>(
            item_emb + (size_t)(nbase + row) * D_)[q4]);
        uint32_t h0 = pack_bf16(v.x, v.y), h1 = pack_bf16(v.z, v.w);
        __nv_bfloat162 b0 = *reinterpret_cast<__nv_bfloat162*>(&h0);
        __nv_bfloat162 b1 = *reinterpret_cast<__nv_bfloat162*>(&h1);
        uint32_t l0 = pack_bf16(v.x - __bfloat162float(b0.x), v.y - __bfloat162float(b0.y));
        uint32_t l1 = pack_bf16(v.z - __bfloat162float(b1.x), v.w - __bfloat162float(b1.y));
        *reinterpret_cast<uint2*>(&bh[row * BSTR2 + q4 * 4]) = make_uint2(h0, h1);
        *reinterpret_cast<uint2*>(&bl[row * BSTR2 + q4 * 4]) = make_uint2(l0, l1);
    }
    __syncthreads();

    const int lg = lane >> 2, q = lane & 3;
    const int rig = lane & 7, mcode = lane >> 3;
    const int j_off = mcode >> 1, khalf = mcode & 1;
    uint32_t bhb = (uint32_t)__cvta_generic_to_shared(bh)
                 + ((j_off * 8 + rig) * BSTR2 + khalf * 8) * 2;
    uint32_t blb = (uint32_t)__cvta_generic_to_shared(bl)
                 + ((j_off * 8 + rig) * BSTR2 + khalf * 8) * 2;

    // hoist ALL B fragments into registers: [kk][j][2], hi and lo
    uint32_t Bfh[4][4][2], Bfl[4][4][2];
#pragma unroll
    for (int kk = 0; kk < 4; kk++)
#pragma unroll
        for (int p = 0; p < 2; p++) {
            uint32_t off = (uint32_t)(p * 16 * BSTR2 * 2 + kk * 32);
            LDSM4(Bfh[kk][2*p][0], Bfh[kk][2*p][1], Bfh[kk][2*p+1][0], Bfh[kk][2*p+1][1], bhb + off);
            LDSM4(Bfl[kk][2*p][0], Bfl[kk][2*p][1], Bfl[kk][2*p+1][0], Bfl[kk][2*p+1][1], blb + off);
        }

    const int mt0 = blockIdx.y * (16 / MSPLIT);
    for (int mt = mt0; mt < mt0 + 16 / MSPLIT; mt++) {
        float acc[4][4];
#pragma unroll
        for (int j = 0; j < 4; j++) {
            acc[j][0]=0.f; acc[j][1]=0.f; acc[j][2]=0.f; acc[j][3]=0.f;
        }

        const int rt = mt * 8 + wm;
#pragma unroll
        for (int kk = 0; kk < 4; kk++) {
            uint4 ah = g_vufh[(rt * 4 + kk) * 32 + lane];
            uint4 al = g_vufl[(rt * 4 + kk) * 32 + lane];
#pragma unroll
            for (int j = 0; j < 4; j++) {
                MMA_BF16(acc[j][0],acc[j][1],acc[j][2],acc[j][3],
                         ah.x,ah.y,ah.z,ah.w, Bfh[kk][j][0],Bfh[kk][j][1]);
                MMA_BF16(acc[j][0],acc[j][1],acc[j][2],acc[j][3],
                         ah.x,ah.y,ah.z,ah.w, Bfl[kk][j][0],Bfl[kk][j][1]);
                MMA_BF16(acc[j][0],acc[j][1],acc[j][2],acc[j][3],
                         al.x,al.y,al.z,al.w, Bfh[kk][j][0],Bfh[kk][j][1]);
            }
        }

        int r0 = rt * 16 + lg;
#pragma unroll
        for (int j = 0; j < 4; j++) {
            int n0 = nbase + j * 8 + 2 * q;
            __stcs(reinterpret_cast<float2*>(out + (size_t)r0 * N_ + n0),
                   make_float2(acc[j][0], acc[j][1]));
            __stcs(reinterpret_cast<float2*>(out + (size_t)(r0 + 8) * N_ + n0),
                   make_float2(acc[j][2], acc[j][3]));
        }
    }
}

extern "C" void kernel_launch(void* const* d_in, const int* in_sizes, int n_in,
                              void* d_out, int out_size) {
    const int* item_seq = (const int*)d_in[0];
    const float* item_emb = (const float*)d_in[2];
    const float* Cg  = (const float*)d_in[3];
    const float* w1  = (const float*)d_in[4];
    const float* w2  = (const float*)d_in[5];
    const float* w3  = (const float*)d_in[6];
    const float* w4  = (const float*)d_in[7];
    const float* wk1 = (const float*)d_in[8];
    const float* wk2 = (const float*)d_in[9];
    const float* ln2w = (const float*)d_in[10];
    const float* ln2b = (const float*)d_in[11];
    const float* ln4w = (const float*)d_in[12];
    const float* ln4b = (const float*)d_in[13];
    float* out = (float*)d_out;

    rowgemm_kernel<<<ROWS_ / 128, 256>>>(item_seq, item_emb, wk1, wk2, w1, w2, w3);
    zu_kernel<<<B_, 64>>>(item_seq, item_emb);
    su_kernel<<<B_ / 16, 256>>>(Cg);
    head_kernel<<<B_, 256>>>(item_seq, item_emb, Cg, w3, w4,
                             ln2w, ln2b, ln4w, ln4b);
    dim3 sg(N_ / 32, MSPLIT);
    scores_frag<<<sg, 256>>>(item_emb, out);
}

// round 15
// speedup vs baseline: 1.2826x; 1.0763x over previous
#include <cuda_runtime.h>
#include <cuda_bf16.h>
#include <cstdint>

#define B_ 2048
#define S_ 50
#define D_ 64
#define L_ 500
#define K_ 4
#define N_ 100000
#define TAU_ 0.1f
#define LN_EPS 1e-12f
#define ROWS_ (B_ * S_)

// v_u in MMA-fragment order (hi/lo): [rowtile 128][kk 4][lane 32] each uint4
__device__ uint4 g_vufh[128 * 4 * 32];
__device__ uint4 g_vufl[128 * 4 * 32];
// rowgemm outputs
__device__ float g_aklog[K_ * ROWS_];
__device__ float g_logit[ROWS_];
__device__ float g_w3n[ROWS_ * D_];
// zu / su
__device__ float g_zu[B_ * D_];
__device__ float g_su[B_ * L_];

__device__ __forceinline__ float warpsum(float v) {
#pragma unroll
    for (int o = 16; o; o >>= 1) v += __shfl_xor_sync(0xffffffffu, v, o);
    return v;
}
__device__ __forceinline__ float warpmax(float v) {
#pragma unroll
    for (int o = 16; o; o >>= 1) v = fmaxf(v, __shfl_xor_sync(0xffffffffu, v, o));
    return v;
}
__device__ __forceinline__ uint32_t pack_bf16(float a, float b) {
    __nv_bfloat162 t = __floats2bfloat162_rn(a, b);
    return *reinterpret_cast<uint32_t*>(&t);
}

#define MMA_BF16(d0,d1,d2,d3,a0,a1,a2,a3,b0,b1)                              \
    asm volatile("mma.sync.aligned.m16n8k16.row.col.f32.bf16.bf16.f32 "      \
        "{%0,%1,%2,%3}, {%4,%5,%6,%7}, {%8,%9}, {%0,%1,%2,%3};"              \
        : "+f"(d0), "+f"(d1), "+f"(d2), "+f"(d3)                             \
        : "r"(a0), "r"(a1), "r"(a2), "r"(a3), "r"(b0), "r"(b1))
#define LDSM4(r0,r1,r2,r3,addr)                                              \
    asm volatile("ldmatrix.sync.aligned.m8n8.x4.shared.b16 {%0,%1,%2,%3}, [%4];" \
        : "=r"(r0), "=r"(r1), "=r"(r2), "=r"(r3) : "r"(addr))

// ---------------------------------------------------------------------------
// Kernel 0: rowgemm (unchanged)
// ---------------------------------------------------------------------------
#define ASTR 72
__global__ __launch_bounds__(256) void rowgemm_kernel(
    const int* __restrict__ item_seq, const float* __restrict__ item_emb,
    const float* __restrict__ wk1, const float* __restrict__ wk2,
    const float* __restrict__ w1, const float* __restrict__ w2,
    const float* __restrict__ w3)
{
    __shared__ __align__(16) __nv_bfloat16 Ah[128 * ASTR];
    __shared__ __align__(16) __nv_bfloat16 Al[128 * ASTR];
    __shared__ __align__(16) __nv_bfloat16 Bh[D_ * ASTR];
    __shared__ __align__(16) __nv_bfloat16 Bl[D_ * ASTR];
    __shared__ float wvec[D_];

    const int tid = threadIdx.x, lane = tid & 31, w = tid >> 5;
    const int rbase = blockIdx.x * 128;
    {
        int r = tid >> 1, h = tid & 1;
        int it = __ldg(&item_seq[rbase + r]);
        const float4* ep = reinterpret_cast<const float4*>(item_emb + (size_t)it * D_) + h * 8;
        uint32_t* dh = reinterpret_cast<uint32_t*>(Ah + r * ASTR + h * 32);
        uint32_t* dl = reinterpret_cast<uint32_t*>(Al + r * ASTR + h * 32);
#pragma unroll
        for (int i = 0; i < 8; i++) {
            float4 f = __ldg(&ep[i]);
            uint32_t h0 = pack_bf16(f.x, f.y), h1 = pack_bf16(f.z, f.w);
            __nv_bfloat162 b0 = *reinterpret_cast<__nv_bfloat162*>(&h0);
            __nv_bfloat162 b1 = *reinterpret_cast<__nv_bfloat162*>(&h1);
            dh[2*i] = h0; dh[2*i+1] = h1;
            dl[2*i]   = pack_bf16(f.x - __bfloat162float(b0.x), f.y - __bfloat162float(b0.y));
            dl[2*i+1] = pack_bf16(f.z - __bfloat162float(b1.x), f.w - __bfloat162float(b1.y));
        }
    }
    const int lg = lane >> 2, q = lane & 3;
    const int rig = lane & 7, mcode = lane >> 3;
    const int j_off = mcode >> 1, khalf = mcode & 1;
    const int mbase = w * 16;
    uint32_t aBh = (uint32_t)__cvta_generic_to_shared(Ah)
                 + ((mbase + (lane & 7) + ((lane >> 3) & 1) * 8) * ASTR + ((lane >> 4) * 8)) * 2;
    uint32_t aBl = (uint32_t)__cvta_generic_to_shared(Al)
                 + ((mbase + (lane & 7) + ((lane >> 3) & 1) * 8) * ASTR + ((lane >> 4) * 8)) * 2;
    uint32_t bBh = (uint32_t)__cvta_generic_to_shared(Bh)
                 + ((j_off * 8 + rig) * ASTR + khalf * 8) * 2;
    uint32_t bBl = (uint32_t)__cvta_generic_to_shared(Bl)
                 + ((j_off * 8 + rig) * ASTR + khalf * 8) * 2;
    const int r0g = rbase + mbase + lg, r1g = r0g + 8;

    for (int widx = 0; widx < 6; widx++) {
        __syncthreads();
        const float* W = (widx < 4) ? (wk1 + widx * D_ * D_) : (widx == 4 ? w1 : w3);
        const float4* Wv = reinterpret_cast<const float4*>(W);
#pragma unroll
        for (int i = 0; i < 4; i++) {
            int f = tid + i * 256;
            float4 v = __ldg(&Wv[f]);
            int d = f >> 4, e0 = (f & 15) * 4;
            const float* vv = &v.x;
#pragma unroll
            for (int j = 0; j < 4; j++) {
                float val = vv[j];
                __nv_bfloat16 h = __float2bfloat16(val);
                Bh[(e0 + j) * ASTR + d] = h;
                Bl[(e0 + j) * ASTR + d] = __float2bfloat16(val - __bfloat162float(h));
            }
        }
        if (tid < D_) {
            if (widx < 4)       wvec[tid] = __ldg(&wk2[widx * D_ + tid]);
            else if (widx == 4) wvec[tid] = __ldg(&w2[tid]);
        }
        __syncthreads();

        float acc[8][4];
#pragma unroll
        for (int j = 0; j < 8; j++) { acc[j][0]=0.f; acc[j][1]=0.f; acc[j][2]=0.f; acc[j][3]=0.f; }
#pragma unroll
        for (int kk = 0; kk < 4; kk++) {
            uint32_t ah0,ah1,ah2,ah3, al0,al1,al2,al3;
            LDSM4(ah0,ah1,ah2,ah3, aBh + kk * 32);
            LDSM4(al0,al1,al2,al3, aBl + kk * 32);
#pragma unroll
            for (int p = 0; p < 4; p++) {
                uint32_t b0h,b1h,b2h,b3h, b0l,b1l,b2l,b3l;
                uint32_t off = (uint32_t)(p * 16 * ASTR * 2 + kk * 32);
                LDSM4(b0h,b1h,b2h,b3h, bBh + off);
                LDSM4(b0l,b1l,b2l,b3l, bBl + off);
                int j0 = 2 * p, j1 = 2 * p + 1;
                MMA_BF16(acc[j0][0],acc[j0][1],acc[j0][2],acc[j0][3], ah0,ah1,ah2,ah3, b0h,b1h);
                MMA_BF16(acc[j0][0],acc[j0][1],acc[j0][2],acc[j0][3], ah0,ah1,ah2,ah3, b0l,b1l);
                MMA_BF16(acc[j0][0],acc[j0][1],acc[j0][2],acc[j0][3], al0,al1,al2,al3, b0h,b1h);
                MMA_BF16(acc[j1][0],acc[j1][1],acc[j1][2],acc[j1][3], ah0,ah1,ah2,ah3, b2h,b3h);
                MMA_BF16(acc[j1][0],acc[j1][1],acc[j1][2],acc[j1][3], ah0,ah1,ah2,ah3, b2l,b3l);
                MMA_BF16(acc[j1][0],acc[j1][1],acc[j1][2],acc[j1][3], al0,al1,al2,al3, b2h,b3h);
            }
        }
        if (widx < 5) {
            float s0 = 0.f, s1 = 0.f;
#pragma unroll
            for (int j = 0; j < 8; j++) {
                int e0 = j * 8 + 2 * q;
                float w0 = wvec[e0], w1v = wvec[e0 + 1];
                s0 += tanhf(acc[j][0]) * w0 + tanhf(acc[j][1]) * w1v;
                s1 += tanhf(acc[j][2]) * w0 + tanhf(acc[j][3]) * w1v;
            }
            s0 += __shfl_xor_sync(0xffffffffu, s0, 1);
            s0 += __shfl_xor_sync(0xffffffffu, s0, 2);
            s1 += __shfl_xor_sync(0xffffffffu, s1, 1);
            s1 += __shfl_xor_sync(0xffffffffu, s1, 2);
            if (q == 0) {
                if (widx < 4) { g_aklog[widx * ROWS_ + r0g] = s0; g_aklog[widx * ROWS_ + r1g] = s1; }
                else          { g_logit[r0g] = s0; g_logit[r1g] = s1; }
            }
        } else {
            float n0 = 0.f, n1 = 0.f;
#pragma unroll
            for (int j = 0; j < 8; j++) {
                n0 += acc[j][0]*acc[j][0] + acc[j][1]*acc[j][1];
                n1 += acc[j][2]*acc[j][2] + acc[j][3]*acc[j][3];
            }
            n0 += __shfl_xor_sync(0xffffffffu, n0, 1);
            n0 += __shfl_xor_sync(0xffffffffu, n0, 2);
            n1 += __shfl_xor_sync(0xffffffffu, n1, 1);
            n1 += __shfl_xor_sync(0xffffffffu, n1, 2);
            float inv0 = 1.f / fmaxf(sqrtf(n0), 1e-12f);
            float inv1 = 1.f / fmaxf(sqrtf(n1), 1e-12f);
#pragma unroll
            for (int j = 0; j < 8; j++) {
                int c0 = j * 8 + 2 * q;
                *reinterpret_cast<float2*>(g_w3n + (size_t)r0g * D_ + c0) =
                    make_float2(acc[j][0] * inv0, acc[j][1] * inv0);
                *reinterpret_cast<float2*>(g_w3n + (size_t)r1g * D_ + c0) =
                    make_float2(acc[j][2] * inv1, acc[j][3] * inv1);
            }
        }
    }
}

// ---------------------------------------------------------------------------
// Kernel 1: zu (unchanged)
// ---------------------------------------------------------------------------
__global__ __launch_bounds__(64) void zu_kernel(
    const int* __restrict__ item_seq, const float* __restrict__ item_emb)
{
    __shared__ float aw[S_];
    __shared__ int   seqs[S_];
    __shared__ __align__(16) float4 part[4][16];
    const int b = blockIdx.x, tid = threadIdx.x;
    if (tid < S_) seqs[tid] = __ldg(&item_seq[b * S_ + tid]);
    if (tid < 32) {
        const float* lp = g_logit + b * S_;
        float v0 = (tid < S_) ? lp[tid] : -1e30f;
        float v1 = (tid + 32 < S_) ? lp[tid + 32] : -1e30f;
        float m = warpmax(fmaxf(v0, v1));
        float e0 = (tid < S_) ? expf(v0 - m) : 0.f;
        float e1 = (tid + 32 < S_) ? expf(v1 - m) : 0.f;
        float inv = 1.f / warpsum(e0 + e1);
        if (tid < S_) aw[tid] = e0 * inv;
        if (tid + 32 < S_) aw[tid + 32] = e1 * inv;
    }
    __syncthreads();
    int qd = tid & 15, strip = tid >> 4;
    float4 acc = make_float4(0.f, 0.f, 0.f, 0.f);
    for (int s = strip; s < S_; s += 4) {
        const float4* xp = reinterpret_cast<const float4*>(item_emb + (size_t)seqs[s] * D_);
        float4 x = __ldg(&xp[qd]);
        float a = aw[s];
        acc.x = fmaf(a, x.x, acc.x); acc.y = fmaf(a, x.y, acc.y);
        acc.z = fmaf(a, x.z, acc.z); acc.w = fmaf(a, x.w, acc.w);
    }
    part[strip][qd] = acc;
    __syncthreads();
    if (tid < 16) {
        float4 a = part[0][tid], b1 = part[1][tid], c = part[2][tid], d = part[3][tid];
        reinterpret_cast<float4*>(g_zu + b * D_)[tid] =
            make_float4(a.x+b1.x+c.x+d.x, a.y+b1.y+c.y+d.y, a.z+b1.z+c.z+d.z, a.w+b1.w+c.w+d.w);
    }
}

// ---------------------------------------------------------------------------
// Kernel 2: su (unchanged)
// ---------------------------------------------------------------------------
__global__ __launch_bounds__(256) void su_kernel(const float* __restrict__ Cg)
{
    __shared__ __align__(16) float Zs[16][D_];
    const int tid = threadIdx.x, bbase = blockIdx.x * 16;
    for (int i = tid; i < 16 * 16; i += 256) {
        int j = i >> 4, q = i & 15;
        reinterpret_cast<float4*>(&Zs[j][0])[q] =
            reinterpret_cast<const float4*>(g_zu + (bbase + j) * D_)[q];
    }
    __syncthreads();
    for (int l = tid; l < L_; l += 256) {
        float acc[16];
#pragma unroll
        for (int j = 0; j < 16; j++) acc[j] = 0.f;
        const float4* cr = reinterpret_cast<const float4*>(Cg + l * D_);
#pragma unroll
        for (int dq = 0; dq < 16; dq++) {
            float4 c = __ldg(&cr[dq]);
#pragma unroll
            for (int j = 0; j < 16; j++) {
                acc[j] = fmaf(c.x, Zs[j][4*dq],   acc[j]);
                acc[j] = fmaf(c.y, Zs[j][4*dq+1], acc[j]);
                acc[j] = fmaf(c.z, Zs[j][4*dq+2], acc[j]);
                acc[j] = fmaf(c.w, Zs[j][4*dq+3], acc[j]);
            }
        }
#pragma unroll
        for (int j = 0; j < 16; j++) g_su[(bbase + j) * L_ + l] = acc[j];
    }
}

// ---------------------------------------------------------------------------
// Kernel 3: head — step 13 replaced by rank-4 factorization:
//   x_u_bar @ w3 = Pktb @ (Cu @ w3);  capt = sum_k pk[k]*Cu[k]
// ---------------------------------------------------------------------------
__global__ __launch_bounds__(256) void head_kernel(
    const int* __restrict__ item_seq, const float* __restrict__ item_emb,
    const float* __restrict__ Cg,
    const float* __restrict__ w3, const float* __restrict__ w4,
    const float* __restrict__ ln2w, const float* __restrict__ ln2b,
    const float* __restrict__ ln4w, const float* __restrict__ ln4b)
{
    __shared__ __align__(16) float xu[S_][D_];
    __shared__ __align__(16) float buf2[S_][D_];   // w3n only
    __shared__ int   seqs[S_];
    __shared__ float logit[S_];
    __shared__ float aw[S_];
    __shared__ __align__(16) float su[L_];
    __shared__ float selv[K_];
    __shared__ int   seli[K_];
    __shared__ float stopv[K_];
    __shared__ int   sidx[K_];
    __shared__ __align__(16) float Cu[K_][D_];
    __shared__ __align__(16) float Cun[K_][D_];
    __shared__ __align__(16) float Pktb[S_][K_];
    __shared__ float mulp[K_][S_];
    __shared__ __align__(16) float delta[K_][D_];
    __shared__ float nrm2[K_];
    __shared__ float capt[D_];
    __shared__ float ekw[K_];
    __shared__ float vstage[D_];
    __shared__ float cw3[K_][D_];
    __shared__ float pks[K_];

    const int b = blockIdx.x, tid = threadIdx.x, lane = tid & 31, w = tid >> 5;

    if (tid < S_) seqs[tid] = __ldg(&item_seq[b * S_ + tid]);
    if (tid < 125)
        reinterpret_cast<float4*>(su)[tid] =
            __ldg(&reinterpret_cast<const float4*>(g_su + b * L_)[tid]);
    __syncthreads();
    {
        for (int i = tid; i < S_ * 16; i += 256) {
            int s = i >> 4, q = i & 15;
            const float4* ep = reinterpret_cast<const float4*>(item_emb + (size_t)seqs[s] * D_);
            reinterpret_cast<float4*>(&xu[s][0])[q] = __ldg(&ep[q]);
        }
        const float4* wp = reinterpret_cast<const float4*>(g_w3n + (size_t)b * S_ * D_);
        for (int i = tid; i < S_ * 16; i += 256) {
            int s = i >> 4, q = i & 15;
            reinterpret_cast<float4*>(&buf2[s][0])[q] = __ldg(&wp[i]);
        }
    }
    __syncthreads();

    // ---- top-4 (stable ascending argsort -> last 4, ascending) ----
    if (w == 0) {
        for (int r = 0; r < K_; r++) {
            float mv = -1e30f; int mi = -1;
            for (int l = lane; l < L_; l += 32) {
                bool skip = false;
#pragma unroll
                for (int t = 0; t < K_; t++)
                    if (t < r && seli[t] == l) skip = true;
                float v = su[l];
                if (!skip && (v > mv || (v == mv && l > mi))) { mv = v; mi = l; }
            }
#pragma unroll
            for (int o = 16; o; o >>= 1) {
                float ov = __shfl_xor_sync(0xffffffffu, mv, o);
                int   oi = __shfl_xor_sync(0xffffffffu, mi, o);
                if (ov > mv || (ov == mv && oi > mi)) { mv = ov; mi = oi; }
            }
            if (lane == 0) { seli[r] = mi; selv[r] = mv; }
            __syncwarp();
        }
        if (lane < K_) { sidx[lane] = seli[K_ - 1 - lane]; stopv[lane] = selv[K_ - 1 - lane]; }
    }
    __syncthreads();

    // ---- C_u, C_u_norm ----
    if (w < K_) {
        int k = w;
        float sg = 1.f / (1.f + expf(-stopv[k]));
        const float* cr = Cg + sidx[k] * D_;
        float v0 = __ldg(&cr[lane]) * sg;
        float v1 = __ldg(&cr[lane + 32]) * sg;
        Cu[k][lane] = v0; Cu[k][lane + 32] = v1;
        float mean = warpsum(v0 + v1) * (1.f / 64.f);
        float d0 = v0 - mean, d1 = v1 - mean;
        float var = warpsum(d0 * d0 + d1 * d1) * (1.f / 64.f);
        float inv = rsqrtf(var + LN_EPS);
        Cun[k][lane]      = d0 * inv * __ldg(&ln2w[lane])      + __ldg(&ln2b[lane]);
        Cun[k][lane + 32] = d1 * inv * __ldg(&ln2w[lane + 32]) + __ldg(&ln2b[lane + 32]);
    }
    __syncthreads();

    // ---- P_k_t + softmax over k ----
    if (tid < S_ * K_) {
        int s = tid >> 2, k = tid & 3;
        const float4* bp = reinterpret_cast<const float4*>(&buf2[s][0]);
        const float4* cp = reinterpret_cast<const float4*>(&Cun[k][0]);
        float acc = 0.f;
#pragma unroll
        for (int q = 0; q < 16; q++) {
            float4 x = bp[q], c = cp[q];
            acc += x.x*c.x + x.y*c.y + x.z*c.z + x.w*c.w;
        }
        Pktb[s][k] = acc;
    }
    __syncthreads();
    if (tid < S_) {
        float v0 = Pktb[tid][0], v1 = Pktb[tid][1], v2 = Pktb[tid][2], v3 = Pktb[tid][3];
        float m = fmaxf(fmaxf(v0, v1), fmaxf(v2, v3));
        float e0 = expf(v0 - m), e1 = expf(v1 - m), e2 = expf(v2 - m), e3 = expf(v3 - m);
        float inv = 1.f / (e0 + e1 + e2 + e3);
        Pktb[tid][0] = e0 * inv; Pktb[tid][1] = e1 * inv;
        Pktb[tid][2] = e2 * inv; Pktb[tid][3] = e3 * inv;
    }
    __syncthreads();

    // ---- P_t_k softmax from aklog; mulp ----
    if (w < K_) {
        int k = w;
        const float* akr = g_aklog + k * ROWS_ + b * S_;
        float v0 = (lane < S_) ? akr[lane] : -1e30f;
        float v1 = (lane + 32 < S_) ? akr[lane + 32] : -1e30f;
        float m = warpmax(fmaxf(v0, v1));
        float e0 = (lane < S_) ? expf(v0 - m) : 0.f;
        float e1 = (lane + 32 < S_) ? expf(v1 - m) : 0.f;
        float inv = 1.f / warpsum(e0 + e1);
        if (lane < S_) mulp[k][lane] = Pktb[lane][k] * e0 * inv;
        if (lane + 32 < S_) mulp[k][lane + 32] = Pktb[lane + 32][k] * e1 * inv;
    }
    __syncthreads();

    // ---- delta_raw (warps 0-3) + cw3 = Cu @ w3 (all 8 warps) ----
    if (tid < 128) {
        int k = tid >> 5, d2 = tid & 31;
        float2 acc = make_float2(0.f, 0.f);
#pragma unroll
        for (int s = 0; s < S_; s++) {
            float m = mulp[k][s];
            float2 x = *reinterpret_cast<const float2*>(&xu[s][2 * d2]);
            acc.x = fmaf(m, x.x, acc.x);
            acc.y = fmaf(m, x.y, acc.y);
        }
        *reinterpret_cast<float2*>(&delta[k][2 * d2]) = acc;
    }
    {
        int k = w & 3;
        int e0 = (w >> 2) * 32 + lane;
        float acc = 0.f;
#pragma unroll 8
        for (int d = 0; d < D_; d++)
            acc = fmaf(Cu[k][d], __ldg(&w3[d * D_ + e0]), acc);
        cw3[k][e0] = acc;
    }
    __syncthreads();

    // ---- normalize delta ----
    if (w < K_) {
        int k = w;
        float d0 = delta[k][lane], d1 = delta[k][lane + 32];
        float n = warpsum(d0 * d0 + d1 * d1);
        if (lane == 0) nrm2[k] = 1.f / fmaxf(sqrtf(n), 1e-12f);
    }
    __syncthreads();
    {
        int k = tid >> 6, d = tid & 63;
        delta[k][d] *= nrm2[k];
    }

    // ---- logit2[s] = sum_e tanh(sum_k Pktb[s][k]*cw3[k][e]) * w4[e] ----
    {
        const float w4a = __ldg(&w4[2 * lane]);
        const float w4b = __ldg(&w4[2 * lane + 1]);
        float c0a = cw3[0][2*lane], c0b = cw3[0][2*lane+1];
        float c1a = cw3[1][2*lane], c1b = cw3[1][2*lane+1];
        float c2a = cw3[2][2*lane], c2b = cw3[2][2*lane+1];
        float c3a = cw3[3][2*lane], c3b = cw3[3][2*lane+1];
#pragma unroll
        for (int c = 0; c < 7; c++) {
            int s = w + 8 * c;
            if (s < S_) {
                float p0 = Pktb[s][0], p1 = Pktb[s][1], p2 = Pktb[s][2], p3 = Pktb[s][3];
                float a0 = p0*c0a + p1*c1a + p2*c2a + p3*c3a;
                float a1 = p0*c0b + p1*c1b + p2*c2b + p3*c3b;
                float t = tanhf(a0) * w4a + tanhf(a1) * w4b;
                t = warpsum(t);
                if (lane == 0) logit[s] = t;
            }
        }
    }
    __syncthreads();
    if (w == 0) {
        float v0 = (lane < S_) ? logit[lane] : -1e30f;
        float v1 = (lane + 32 < S_) ? logit[lane + 32] : -1e30f;
        float m = warpmax(fmaxf(v0, v1));
        float e0 = (lane < S_) ? expf(v0 - m) : 0.f;
        float e1 = (lane + 32 < S_) ? expf(v1 - m) : 0.f;
        float inv = 1.f / warpsum(e0 + e1);
        if (lane < S_) aw[lane] = e0 * inv;
        if (lane + 32 < S_) aw[lane + 32] = e1 * inv;
    }
    __syncthreads();

    // ---- pk[k] = sum_s aw[s]*Pktb[s][k]; capt = sum_k pk[k]*Cu[k] ----
    if (w < K_) {
        int k = w;
        float p = ((lane < S_) ? aw[lane] * Pktb[lane][k] : 0.f)
                + ((lane + 32 < S_) ? aw[lane + 32] * Pktb[lane + 32][k] : 0.f);
        p = warpsum(p);
        if (lane == 0) pks[k] = p;
    }
    __syncthreads();
    if (tid < D_) {
        capt[tid] = pks[0]*Cu[0][tid] + pks[1]*Cu[1][tid]
                  + pks[2]*Cu[2][tid] + pks[3]*Cu[3][tid];
    }
    __syncthreads();
    if (w == 0) {
        float c0 = capt[lane], c1 = capt[lane + 32];
        float mean = warpsum(c0 + c1) * (1.f / 64.f);
        float d0 = c0 - mean, d1 = c1 - mean;
        float var = warpsum(d0 * d0 + d1 * d1) * (1.f / 64.f);
        float inv = rsqrtf(var + LN_EPS);
        capt[lane]      = d0 * inv * __ldg(&ln4w[lane])      + __ldg(&ln4b[lane]);
        capt[lane + 32] = d1 * inv * __ldg(&ln4w[lane + 32]) + __ldg(&ln4b[lane + 32]);
    }
    __syncthreads();

    // ---- e_k softmax; v_u ----
    if (w < K_) {
        int k = w;
        float p = delta[k][lane] * capt[lane] + delta[k][lane + 32] * capt[lane + 32];
        p = warpsum(p) * (1.f / TAU_);
        if (lane == 0) ekw[k] = p;
    }
    __syncthreads();
    if (tid == 0) {
        float m = fmaxf(fmaxf(ekw[0], ekw[1]), fmaxf(ekw[2], ekw[3]));
        float e0 = expf(ekw[0] - m), e1 = expf(ekw[1] - m);
        float e2 = expf(ekw[2] - m), e3 = expf(ekw[3] - m);
        float inv = 1.f / (e0 + e1 + e2 + e3);
        ekw[0] = e0 * inv; ekw[1] = e1 * inv; ekw[2] = e2 * inv; ekw[3] = e3 * inv;
    }
    __syncthreads();
    if (tid < D_) {
        vstage[tid] = ekw[0] * delta[0][tid] + ekw[1] * delta[1][tid]
                    + ekw[2] * delta[2][tid] + ekw[3] * delta[3][tid];
    }
    __syncthreads();
    if (tid < 32) {
        int j = tid;
        float v0 = vstage[2 * j], v1 = vstage[2 * j + 1];
        __nv_bfloat16 h0 = __float2bfloat16(v0), h1 = __float2bfloat16(v1);
        uint32_t hw = pack_bf16(v0, v1);
        uint32_t lw = pack_bf16(v0 - __bfloat162float(h0), v1 - __bfloat162float(h1));
        int rt = b >> 4, rr = b & 15;
        int role = rr >> 3, lg2 = rr & 7;
        int kk = j >> 3, t = j & 7, q2 = t & 3, h8 = t >> 2;
        int lane2 = lg2 * 4 + q2;
        int slot = role + 2 * h8;
        int frag = (rt * 4 + kk) * 32 + lane2;
        reinterpret_cast<uint32_t*>(&g_vufh[frag])[slot] = hw;
        reinterpret_cast<uint32_t*>(&g_vufl[frag])[slot] = lw;
    }
}

// ---------------------------------------------------------------------------
// Kernel 4: scores — round-11 exact (register-resident B, 128 thr, MSPLIT=2).
// ---------------------------------------------------------------------------
#define BSTR2 72
#define MSPLIT 2
__global__ __launch_bounds__(128) void scores_frag(
    const float* __restrict__ item_emb,
    float* __restrict__ out)
{
    __shared__ __align__(16) __nv_bfloat16 bh[32 * BSTR2];
    __shared__ __align__(16) __nv_bfloat16 bl[32 * BSTR2];

    const int tid = threadIdx.x, lane = tid & 31, wm = tid >> 5;
    const int nbase = blockIdx.x * 32;

    for (int i = tid; i < 512; i += 128) {
        int row = i >> 4, q4 = i & 15;
        float4 v = __ldg(&reinterpret_cast<const float4*>(
            item_emb + (size_t)(nbase + row) * D_)[q4]);
        uint32_t h0 = pack_bf16(v.x, v.y), h1 = pack_bf16(v.z, v.w);
        __nv_bfloat162 b0 = *reinterpret_cast<__nv_bfloat162*>(&h0);
        __nv_bfloat162 b1 = *reinterpret_cast<__nv_bfloat162*>(&h1);
        uint32_t l0 = pack_bf16(v.x - __bfloat162float(b0.x), v.y - __bfloat162float(b0.y));
        uint32_t l1 = pack_bf16(v.z - __bfloat162float(b1.x), v.w - __bfloat162float(b1.y));
        *reinterpret_cast<uint2*>(&bh[row * BSTR2 + q4 * 4]) = make_uint2(h0, h1);
        *reinterpret_cast<uint2*>(&bl[row * BSTR2 + q4 * 4]) = make_uint2(l0, l1);
    }
    __syncthreads();

    const int lg = lane >> 2, q = lane & 3;
    const int rig = lane & 7, mcode = lane >> 3;
    const int j_off = mcode >> 1, khalf = mcode & 1;
    uint32_t bhb = (uint32_t)__cvta_generic_to_shared(bh)
                 + ((j_off * 8 + rig) * BSTR2 + khalf * 8) * 2;
    uint32_t blb = (uint32_t)__cvta_generic_to_shared(bl)
                 + ((j_off * 8 + rig) * BSTR2 + khalf * 8) * 2;

    uint32_t Bfh[4][4][2], Bfl[4][4][2];
#pragma unroll
    for (int kk = 0; kk < 4; kk++)
#pragma unroll
        for (int p = 0; p < 2; p++) {
            uint32_t off = (uint32_t)(p * 16 * BSTR2 * 2 + kk * 32);
            LDSM4(Bfh[kk][2*p][0], Bfh[kk][2*p][1], Bfh[kk][2*p+1][0], Bfh[kk][2*p+1][1], bhb + off);
            LDSM4(Bfl[kk][2*p][0], Bfl[kk][2*p][1], Bfl[kk][2*p+1][0], Bfl[kk][2*p+1][1], blb + off);
        }

    const int mt0 = blockIdx.y * (16 / MSPLIT);
    for (int mt = mt0; mt < mt0 + 16 / MSPLIT; mt++) {
        float acc[2][4][4];
#pragma unroll
        for (int f = 0; f < 2; f++)
#pragma unroll
            for (int j = 0; j < 4; j++) {
                acc[f][j][0]=0.f; acc[f][j][1]=0.f; acc[f][j][2]=0.f; acc[f][j][3]=0.f;
            }

        const int rt0 = mt * 8 + wm * 2;
#pragma unroll
        for (int kk = 0; kk < 4; kk++) {
            uint4 ah0 = g_vufh[(rt0 * 4 + kk) * 32 + lane];
            uint4 ah1 = g_vufh[((rt0 + 1) * 4 + kk) * 32 + lane];
            uint4 al0 = g_vufl[(rt0 * 4 + kk) * 32 + lane];
            uint4 al1 = g_vufl[((rt0 + 1) * 4 + kk) * 32 + lane];
#pragma unroll
            for (int j = 0; j < 4; j++) {
                MMA_BF16(acc[0][j][0],acc[0][j][1],acc[0][j][2],acc[0][j][3],
                         ah0.x,ah0.y,ah0.z,ah0.w, Bfh[kk][j][0],Bfh[kk][j][1]);
                MMA_BF16(acc[0][j][0],acc[0][j][1],acc[0][j][2],acc[0][j][3],
                         ah0.x,ah0.y,ah0.z,ah0.w, Bfl[kk][j][0],Bfl[kk][j][1]);
                MMA_BF16(acc[0][j][0],acc[0][j][1],acc[0][j][2],acc[0][j][3],
                         al0.x,al0.y,al0.z,al0.w, Bfh[kk][j][0],Bfh[kk][j][1]);
                MMA_BF16(acc[1][j][0],acc[1][j][1],acc[1][j][2],acc[1][j][3],
                         ah1.x,ah1.y,ah1.z,ah1.w, Bfh[kk][j][0],Bfh[kk][j][1]);
                MMA_BF16(acc[1][j][0],acc[1][j][1],acc[1][j][2],acc[1][j][3],
                         ah1.x,ah1.y,ah1.z,ah1.w, Bfl[kk][j][0],Bfl[kk][j][1]);
                MMA_BF16(acc[1][j][0],acc[1][j][1],acc[1][j][2],acc[1][j][3],
                         al1.x,al1.y,al1.z,al1.w, Bfh[kk][j][0],Bfh[kk][j][1]);
            }
        }

#pragma unroll
        for (int f = 0; f < 2; f++) {
            int r0 = mt * 128 + wm * 32 + f * 16 + lg;
#pragma unroll
            for (int j = 0; j < 4; j++) {
                int n0 = nbase + j * 8 + 2 * q;
                __stcs(reinterpret_cast<float2*>(out + (size_t)r0 * N_ + n0),
                       make_float2(acc[f][j][0], acc[f][j][1]));
                __stcs(reinterpret_cast<float2*>(out + (size_t)(r0 + 8) * N_ + n0),
                       make_float2(acc[f][j][2], acc[f][j][3]));
            }
        }
    }
}

extern "C" void kernel_launch(void* const* d_in, const int* in_sizes, int n_in,
                              void* d_out, int out_size) {
    const int* item_seq = (const int*)d_in[0];
    const float* item_emb = (const float*)d_in[2];
    const float* Cg  = (const float*)d_in[3];
    const float* w1  = (const float*)d_in[4];
    const float* w2  = (const float*)d_in[5];
    const float* w3  = (const float*)d_in[6];
    const float* w4  = (const float*)d_in[7];
    const float* wk1 = (const float*)d_in[8];
    const float* wk2 = (const float*)d_in[9];
    const float* ln2w = (const float*)d_in[10];
    const float* ln2b = (const float*)d_in[11];
    const float* ln4w = (const float*)d_in[12];
    const float* ln4b = (const float*)d_in[13];
    float* out = (float*)d_out;

    rowgemm_kernel<<<ROWS_ / 128, 256>>>(item_seq, item_emb, wk1, wk2, w1, w2, w3);
    zu_kernel<<<B_, 64>>>(item_seq, item_emb);
    su_kernel<<<B_ / 16, 256>>>(Cg);
    head_kernel<<<B_, 256>>>(item_seq, item_emb, Cg, w3, w4,
                             ln2w, ln2b, ln4w, ln4b);
    dim3 sg(N_ / 32, MSPLIT);
    scores_frag<<<sg, 128>>>(item_emb, out);
}

// round 16
// speedup vs baseline: 1.3474x; 1.0506x over previous
#include <cuda_runtime.h>
#include <cuda_bf16.h>
#include <cstdint>

#define B_ 2048
#define S_ 50
#define D_ 64
#define L_ 500
#define K_ 4
#define N_ 100000
#define TAU_ 0.1f
#define LN_EPS 1e-12f
#define ROWS_ (B_ * S_)

// v_u in MMA-fragment order (hi/lo): [rowtile 128][kk 4][lane 32] each uint4
__device__ uint4 g_vufh[128 * 4 * 32];
__device__ uint4 g_vufl[128 * 4 * 32];
// rowgemm outputs
__device__ float g_aklog[K_ * ROWS_];
__device__ float g_logit[ROWS_];
__device__ float g_w3n[ROWS_ * D_];
// zu / su
__device__ float g_zu[B_ * D_];
__device__ float g_su[B_ * L_];
// pre-transposed bf16 hi/lo weights: [widx][e][d] (widx: wk1[0..3], w1, w3)
__device__ __nv_bfloat16 g_wbh[6 * 4096];
__device__ __nv_bfloat16 g_wbl[6 * 4096];

__device__ __forceinline__ float warpsum(float v) {
#pragma unroll
    for (int o = 16; o; o >>= 1) v += __shfl_xor_sync(0xffffffffu, v, o);
    return v;
}
__device__ __forceinline__ float warpmax(float v) {
#pragma unroll
    for (int o = 16; o; o >>= 1) v = fmaxf(v, __shfl_xor_sync(0xffffffffu, v, o));
    return v;
}
__device__ __forceinline__ uint32_t pack_bf16(float a, float b) {
    __nv_bfloat162 t = __floats2bfloat162_rn(a, b);
    return *reinterpret_cast<uint32_t*>(&t);
}

#define MMA_BF16(d0,d1,d2,d3,a0,a1,a2,a3,b0,b1)                              \
    asm volatile("mma.sync.aligned.m16n8k16.row.col.f32.bf16.bf16.f32 "      \
        "{%0,%1,%2,%3}, {%4,%5,%6,%7}, {%8,%9}, {%0,%1,%2,%3};"              \
        : "+f"(d0), "+f"(d1), "+f"(d2), "+f"(d3)                             \
        : "r"(a0), "r"(a1), "r"(a2), "r"(a3), "r"(b0), "r"(b1))
#define LDSM4(r0,r1,r2,r3,addr)                                              \
    asm volatile("ldmatrix.sync.aligned.m8n8.x4.shared.b16 {%0,%1,%2,%3}, [%4];" \
        : "=r"(r0), "=r"(r1), "=r"(r2), "=r"(r3) : "r"(addr))

// ---------------------------------------------------------------------------
// Kernel -1: wprep — convert 6 weight matrices to transposed bf16 hi/lo.
// ---------------------------------------------------------------------------
__global__ __launch_bounds__(256) void wprep_kernel(
    const float* __restrict__ wk1, const float* __restrict__ w1,
    const float* __restrict__ w3)
{
    const int widx = blockIdx.x;
    const float* W = (widx < 4) ? (wk1 + widx * 4096) : (widx == 4 ? w1 : w3);
    __nv_bfloat16* dh = g_wbh + widx * 4096;
    __nv_bfloat16* dl = g_wbl + widx * 4096;
    for (int idx = threadIdx.x; idx < 4096; idx += 256) {
        int d = idx >> 6, e = idx & 63;
        float v = __ldg(&W[idx]);
        __nv_bfloat16 h = __float2bfloat16(v);
        dh[e * 64 + d] = h;
        dl[e * 64 + d] = __float2bfloat16(v - __bfloat162float(h));
    }
}

// ---------------------------------------------------------------------------
// Kernel 0: rowgemm — weight staging is now a packed copy from g_wbh/g_wbl.
// ---------------------------------------------------------------------------
#define ASTR 72
__global__ __launch_bounds__(256) void rowgemm_kernel(
    const int* __restrict__ item_seq, const float* __restrict__ item_emb,
    const float* __restrict__ wk2, const float* __restrict__ w2)
{
    __shared__ __align__(16) __nv_bfloat16 Ah[128 * ASTR];
    __shared__ __align__(16) __nv_bfloat16 Al[128 * ASTR];
    __shared__ __align__(16) __nv_bfloat16 Bh[D_ * ASTR];
    __shared__ __align__(16) __nv_bfloat16 Bl[D_ * ASTR];
    __shared__ float wvec[D_];

    const int tid = threadIdx.x, lane = tid & 31, w = tid >> 5;
    const int rbase = blockIdx.x * 128;
    {
        int r = tid >> 1, h = tid & 1;
        int it = __ldg(&item_seq[rbase + r]);
        const float4* ep = reinterpret_cast<const float4*>(item_emb + (size_t)it * D_) + h * 8;
        uint32_t* dh = reinterpret_cast<uint32_t*>(Ah + r * ASTR + h * 32);
        uint32_t* dl = reinterpret_cast<uint32_t*>(Al + r * ASTR + h * 32);
#pragma unroll
        for (int i = 0; i < 8; i++) {
            float4 f = __ldg(&ep[i]);
            uint32_t h0 = pack_bf16(f.x, f.y), h1 = pack_bf16(f.z, f.w);
            __nv_bfloat162 b0 = *reinterpret_cast<__nv_bfloat162*>(&h0);
            __nv_bfloat162 b1 = *reinterpret_cast<__nv_bfloat162*>(&h1);
            dh[2*i] = h0; dh[2*i+1] = h1;
            dl[2*i]   = pack_bf16(f.x - __bfloat162float(b0.x), f.y - __bfloat162float(b0.y));
            dl[2*i+1] = pack_bf16(f.z - __bfloat162float(b1.x), f.w - __bfloat162float(b1.y));
        }
    }
    const int lg = lane >> 2, q = lane & 3;
    const int rig = lane & 7, mcode = lane >> 3;
    const int j_off = mcode >> 1, khalf = mcode & 1;
    const int mbase = w * 16;
    uint32_t aBh = (uint32_t)__cvta_generic_to_shared(Ah)
                 + ((mbase + (lane & 7) + ((lane >> 3) & 1) * 8) * ASTR + ((lane >> 4) * 8)) * 2;
    uint32_t aBl = (uint32_t)__cvta_generic_to_shared(Al)
                 + ((mbase + (lane & 7) + ((lane >> 3) & 1) * 8) * ASTR + ((lane >> 4) * 8)) * 2;
    uint32_t bBh = (uint32_t)__cvta_generic_to_shared(Bh)
                 + ((j_off * 8 + rig) * ASTR + khalf * 8) * 2;
    uint32_t bBl = (uint32_t)__cvta_generic_to_shared(Bl)
                 + ((j_off * 8 + rig) * ASTR + khalf * 8) * 2;
    const int r0g = rbase + mbase + lg, r1g = r0g + 8;

    for (int widx = 0; widx < 6; widx++) {
        __syncthreads();
        // ---- stage weight^T hi/lo: packed uint4 copies ----
        {
            const uint4* sH = reinterpret_cast<const uint4*>(g_wbh + widx * 4096);
            const uint4* sL = reinterpret_cast<const uint4*>(g_wbl + widx * 4096);
#pragma unroll
            for (int i = 0; i < 2; i++) {
                int idx = tid + i * 256;            // 0..511 (uint4 = 8 bf16)
                int e = idx >> 3, d8 = (idx & 7) * 8;
                *reinterpret_cast<uint4*>(&Bh[e * ASTR + d8]) = __ldg(&sH[idx]);
                *reinterpret_cast<uint4*>(&Bl[e * ASTR + d8]) = __ldg(&sL[idx]);
            }
        }
        if (tid < D_) {
            if (widx < 4)       wvec[tid] = __ldg(&wk2[widx * D_ + tid]);
            else if (widx == 4) wvec[tid] = __ldg(&w2[tid]);
        }
        __syncthreads();

        float acc[8][4];
#pragma unroll
        for (int j = 0; j < 8; j++) { acc[j][0]=0.f; acc[j][1]=0.f; acc[j][2]=0.f; acc[j][3]=0.f; }
#pragma unroll
        for (int kk = 0; kk < 4; kk++) {
            uint32_t ah0,ah1,ah2,ah3, al0,al1,al2,al3;
            LDSM4(ah0,ah1,ah2,ah3, aBh + kk * 32);
            LDSM4(al0,al1,al2,al3, aBl + kk * 32);
#pragma unroll
            for (int p = 0; p < 4; p++) {
                uint32_t b0h,b1h,b2h,b3h, b0l,b1l,b2l,b3l;
                uint32_t off = (uint32_t)(p * 16 * ASTR * 2 + kk * 32);
                LDSM4(b0h,b1h,b2h,b3h, bBh + off);
                LDSM4(b0l,b1l,b2l,b3l, bBl + off);
                int j0 = 2 * p, j1 = 2 * p + 1;
                MMA_BF16(acc[j0][0],acc[j0][1],acc[j0][2],acc[j0][3], ah0,ah1,ah2,ah3, b0h,b1h);
                MMA_BF16(acc[j0][0],acc[j0][1],acc[j0][2],acc[j0][3], ah0,ah1,ah2,ah3, b0l,b1l);
                MMA_BF16(acc[j0][0],acc[j0][1],acc[j0][2],acc[j0][3], al0,al1,al2,al3, b0h,b1h);
                MMA_BF16(acc[j1][0],acc[j1][1],acc[j1][2],acc[j1][3], ah0,ah1,ah2,ah3, b2h,b3h);
                MMA_BF16(acc[j1][0],acc[j1][1],acc[j1][2],acc[j1][3], ah0,ah1,ah2,ah3, b2l,b3l);
                MMA_BF16(acc[j1][0],acc[j1][1],acc[j1][2],acc[j1][3], al0,al1,al2,al3, b2h,b3h);
            }
        }
        if (widx < 5) {
            float s0 = 0.f, s1 = 0.f;
#pragma unroll
            for (int j = 0; j < 8; j++) {
                int e0 = j * 8 + 2 * q;
                float w0 = wvec[e0], w1v = wvec[e0 + 1];
                s0 += tanhf(acc[j][0]) * w0 + tanhf(acc[j][1]) * w1v;
                s1 += tanhf(acc[j][2]) * w0 + tanhf(acc[j][3]) * w1v;
            }
            s0 += __shfl_xor_sync(0xffffffffu, s0, 1);
            s0 += __shfl_xor_sync(0xffffffffu, s0, 2);
            s1 += __shfl_xor_sync(0xffffffffu, s1, 1);
            s1 += __shfl_xor_sync(0xffffffffu, s1, 2);
            if (q == 0) {
                if (widx < 4) { g_aklog[widx * ROWS_ + r0g] = s0; g_aklog[widx * ROWS_ + r1g] = s1; }
                else          { g_logit[r0g] = s0; g_logit[r1g] = s1; }
            }
        } else {
            float n0 = 0.f, n1 = 0.f;
#pragma unroll
            for (int j = 0; j < 8; j++) {
                n0 += acc[j][0]*acc[j][0] + acc[j][1]*acc[j][1];
                n1 += acc[j][2]*acc[j][2] + acc[j][3]*acc[j][3];
            }
            n0 += __shfl_xor_sync(0xffffffffu, n0, 1);
            n0 += __shfl_xor_sync(0xffffffffu, n0, 2);
            n1 += __shfl_xor_sync(0xffffffffu, n1, 1);
            n1 += __shfl_xor_sync(0xffffffffu, n1, 2);
            float inv0 = 1.f / fmaxf(sqrtf(n0), 1e-12f);
            float inv1 = 1.f / fmaxf(sqrtf(n1), 1e-12f);
#pragma unroll
            for (int j = 0; j < 8; j++) {
                int c0 = j * 8 + 2 * q;
                *reinterpret_cast<float2*>(g_w3n + (size_t)r0g * D_ + c0) =
                    make_float2(acc[j][0] * inv0, acc[j][1] * inv0);
                *reinterpret_cast<float2*>(g_w3n + (size_t)r1g * D_ + c0) =
                    make_float2(acc[j][2] * inv1, acc[j][3] * inv1);
            }
        }
    }
}

// ---------------------------------------------------------------------------
// Kernel 1: zu (unchanged)
// ---------------------------------------------------------------------------
__global__ __launch_bounds__(64) void zu_kernel(
    const int* __restrict__ item_seq, const float* __restrict__ item_emb)
{
    __shared__ float aw[S_];
    __shared__ int   seqs[S_];
    __shared__ __align__(16) float4 part[4][16];
    const int b = blockIdx.x, tid = threadIdx.x;
    if (tid < S_) seqs[tid] = __ldg(&item_seq[b * S_ + tid]);
    if (tid < 32) {
        const float* lp = g_logit + b * S_;
        float v0 = (tid < S_) ? lp[tid] : -1e30f;
        float v1 = (tid + 32 < S_) ? lp[tid + 32] : -1e30f;
        float m = warpmax(fmaxf(v0, v1));
        float e0 = (tid < S_) ? expf(v0 - m) : 0.f;
        float e1 = (tid + 32 < S_) ? expf(v1 - m) : 0.f;
        float inv = 1.f / warpsum(e0 + e1);
        if (tid < S_) aw[tid] = e0 * inv;
        if (tid + 32 < S_) aw[tid + 32] = e1 * inv;
    }
    __syncthreads();
    int qd = tid & 15, strip = tid >> 4;
    float4 acc = make_float4(0.f, 0.f, 0.f, 0.f);
    for (int s = strip; s < S_; s += 4) {
        const float4* xp = reinterpret_cast<const float4*>(item_emb + (size_t)seqs[s] * D_);
        float4 x = __ldg(&xp[qd]);
        float a = aw[s];
        acc.x = fmaf(a, x.x, acc.x); acc.y = fmaf(a, x.y, acc.y);
        acc.z = fmaf(a, x.z, acc.z); acc.w = fmaf(a, x.w, acc.w);
    }
    part[strip][qd] = acc;
    __syncthreads();
    if (tid < 16) {
        float4 a = part[0][tid], b1 = part[1][tid], c = part[2][tid], d = part[3][tid];
        reinterpret_cast<float4*>(g_zu + b * D_)[tid] =
            make_float4(a.x+b1.x+c.x+d.x, a.y+b1.y+c.y+d.y, a.z+b1.z+c.z+d.z, a.w+b1.w+c.w+d.w);
    }
}

// ---------------------------------------------------------------------------
// Kernel 2: su (unchanged)
// ---------------------------------------------------------------------------
__global__ __launch_bounds__(256) void su_kernel(const float* __restrict__ Cg)
{
    __shared__ __align__(16) float Zs[16][D_];
    const int tid = threadIdx.x, bbase = blockIdx.x * 16;
    for (int i = tid; i < 16 * 16; i += 256) {
        int j = i >> 4, q = i & 15;
        reinterpret_cast<float4*>(&Zs[j][0])[q] =
            reinterpret_cast<const float4*>(g_zu + (bbase + j) * D_)[q];
    }
    __syncthreads();
    for (int l = tid; l < L_; l += 256) {
        float acc[16];
#pragma unroll
        for (int j = 0; j < 16; j++) acc[j] = 0.f;
        const float4* cr = reinterpret_cast<const float4*>(Cg + l * D_);
#pragma unroll
        for (int dq = 0; dq < 16; dq++) {
            float4 c = __ldg(&cr[dq]);
#pragma unroll
            for (int j = 0; j < 16; j++) {
                acc[j] = fmaf(c.x, Zs[j][4*dq],   acc[j]);
                acc[j] = fmaf(c.y, Zs[j][4*dq+1], acc[j]);
                acc[j] = fmaf(c.z, Zs[j][4*dq+2], acc[j]);
                acc[j] = fmaf(c.w, Zs[j][4*dq+3], acc[j]);
            }
        }
#pragma unroll
        for (int j = 0; j < 16; j++) g_su[(bbase + j) * L_ + l] = acc[j];
    }
}

// ---------------------------------------------------------------------------
// Kernel 3: head — rank-4 factorized (round 15) + parallel two-stage top-4.
// ---------------------------------------------------------------------------
__global__ __launch_bounds__(256) void head_kernel(
    const int* __restrict__ item_seq, const float* __restrict__ item_emb,
    const float* __restrict__ Cg,
    const float* __restrict__ w3, const float* __restrict__ w4,
    const float* __restrict__ ln2w, const float* __restrict__ ln2b,
    const float* __restrict__ ln4w, const float* __restrict__ ln4b)
{
    __shared__ __align__(16) float xu[S_][D_];
    __shared__ __align__(16) float buf2[S_][D_];
    __shared__ int   seqs[S_];
    __shared__ float logit[S_];
    __shared__ float aw[S_];
    __shared__ __align__(16) float su[L_];
    __shared__ float candv[16];
    __shared__ int   candi[16];
    __shared__ float stopv[K_];
    __shared__ int   sidx[K_];
    __shared__ __align__(16) float Cu[K_][D_];
    __shared__ __align__(16) float Cun[K_][D_];
    __shared__ __align__(16) float Pktb[S_][K_];
    __shared__ float mulp[K_][S_];
    __shared__ __align__(16) float delta[K_][D_];
    __shared__ float nrm2[K_];
    __shared__ float capt[D_];
    __shared__ float ekw[K_];
    __shared__ float vstage[D_];
    __shared__ float cw3[K_][D_];
    __shared__ float pks[K_];

    const int b = blockIdx.x, tid = threadIdx.x, lane = tid & 31, w = tid >> 5;

    if (tid < S_) seqs[tid] = __ldg(&item_seq[b * S_ + tid]);
    if (tid < 125)
        reinterpret_cast<float4*>(su)[tid] =
            __ldg(&reinterpret_cast<const float4*>(g_su + b * L_)[tid]);
    __syncthreads();
    {
        for (int i = tid; i < S_ * 16; i += 256) {
            int s = i >> 4, q = i & 15;
            const float4* ep = reinterpret_cast<const float4*>(item_emb + (size_t)seqs[s] * D_);
            reinterpret_cast<float4*>(&xu[s][0])[q] = __ldg(&ep[q]);
        }
        const float4* wp = reinterpret_cast<const float4*>(g_w3n + (size_t)b * S_ * D_);
        for (int i = tid; i < S_ * 16; i += 256) {
            int s = i >> 4, q = i & 15;
            reinterpret_cast<float4*>(&buf2[s][0])[q] = __ldg(&wp[i]);
        }
    }
    __syncthreads();

    // ---- top-4, stage 1: warps 0-3 each find top-4 of a 125-element part ----
    if (w < 4) {
        const int base = w * 125;
        float lv[4]; int li[4];
#pragma unroll
        for (int r = 0; r < 4; r++) {
            float mv = -1e30f; int mi = -1;
            for (int l = base + lane; l < base + 125; l += 32) {
                bool skip = false;
#pragma unroll
                for (int t = 0; t < 4; t++)
                    if (t < r && li[t] == l) skip = true;
                float v = su[l];
                if (!skip && (v > mv || (v == mv && l > mi))) { mv = v; mi = l; }
            }
#pragma unroll
            for (int o = 16; o; o >>= 1) {
                float ov = __shfl_xor_sync(0xffffffffu, mv, o);
                int   oi = __shfl_xor_sync(0xffffffffu, mi, o);
                if (ov > mv || (ov == mv && oi > mi)) { mv = ov; mi = oi; }
            }
            lv[r] = mv; li[r] = mi;
        }
        if (lane < 4) { candv[w * 4 + lane] = lv[lane]; candi[w * 4 + lane] = li[lane]; }
    }
    __syncthreads();
    // ---- stage 2: warp 0 selects global top-4 from 16 candidates ----
    if (w == 0) {
        float cv = (lane < 16) ? candv[lane] : -1e30f;
        int   ci = (lane < 16) ? candi[lane] : -1;
#pragma unroll
        for (int r = 0; r < 4; r++) {
            float mv = cv; int mi = ci;
#pragma unroll
            for (int o = 16; o; o >>= 1) {
                float ov = __shfl_xor_sync(0xffffffffu, mv, o);
                int   oi = __shfl_xor_sync(0xffffffffu, mi, o);
                if (ov > mv || (ov == mv && oi > mi)) { mv = ov; mi = oi; }
            }
            if (ci == mi && ci >= 0) { cv = -1e30f; ci = -1; }  // remove winner
            if (lane == 0) {
                // ascending order: global rank r (descending) -> slot 3-r
                sidx[3 - r] = mi; stopv[3 - r] = mv;
            }
        }
    }
    __syncthreads();

    // ---- C_u, C_u_norm ----
    if (w < K_) {
        int k = w;
        float sg = 1.f / (1.f + expf(-stopv[k]));
        const float* cr = Cg + sidx[k] * D_;
        float v0 = __ldg(&cr[lane]) * sg;
        float v1 = __ldg(&cr[lane + 32]) * sg;
        Cu[k][lane] = v0; Cu[k][lane + 32] = v1;
        float mean = warpsum(v0 + v1) * (1.f / 64.f);
        float d0 = v0 - mean, d1 = v1 - mean;
        float var = warpsum(d0 * d0 + d1 * d1) * (1.f / 64.f);
        float inv = rsqrtf(var + LN_EPS);
        Cun[k][lane]      = d0 * inv * __ldg(&ln2w[lane])      + __ldg(&ln2b[lane]);
        Cun[k][lane + 32] = d1 * inv * __ldg(&ln2w[lane + 32]) + __ldg(&ln2b[lane + 32]);
    }
    __syncthreads();

    // ---- P_k_t + softmax over k ----
    if (tid < S_ * K_) {
        int s = tid >> 2, k = tid & 3;
        const float4* bp = reinterpret_cast<const float4*>(&buf2[s][0]);
        const float4* cp = reinterpret_cast<const float4*>(&Cun[k][0]);
        float acc = 0.f;
#pragma unroll
        for (int q = 0; q < 16; q++) {
            float4 x = bp[q], c = cp[q];
            acc += x.x*c.x + x.y*c.y + x.z*c.z + x.w*c.w;
        }
        Pktb[s][k] = acc;
    }
    __syncthreads();
    if (tid < S_) {
        float v0 = Pktb[tid][0], v1 = Pktb[tid][1], v2 = Pktb[tid][2], v3 = Pktb[tid][3];
        float m = fmaxf(fmaxf(v0, v1), fmaxf(v2, v3));
        float e0 = expf(v0 - m), e1 = expf(v1 - m), e2 = expf(v2 - m), e3 = expf(v3 - m);
        float inv = 1.f / (e0 + e1 + e2 + e3);
        Pktb[tid][0] = e0 * inv; Pktb[tid][1] = e1 * inv;
        Pktb[tid][2] = e2 * inv; Pktb[tid][3] = e3 * inv;
    }
    __syncthreads();

    // ---- P_t_k softmax from aklog; mulp ----
    if (w < K_) {
        int k = w;
        const float* akr = g_aklog + k * ROWS_ + b * S_;
        float v0 = (lane < S_) ? akr[lane] : -1e30f;
        float v1 = (lane + 32 < S_) ? akr[lane + 32] : -1e30f;
        float m = warpmax(fmaxf(v0, v1));
        float e0 = (lane < S_) ? expf(v0 - m) : 0.f;
        float e1 = (lane + 32 < S_) ? expf(v1 - m) : 0.f;
        float inv = 1.f / warpsum(e0 + e1);
        if (lane < S_) mulp[k][lane] = Pktb[lane][k] * e0 * inv;
        if (lane + 32 < S_) mulp[k][lane + 32] = Pktb[lane + 32][k] * e1 * inv;
    }
    __syncthreads();

    // ---- delta_raw (warps 0-3) + cw3 = Cu @ w3 (all 8 warps) ----
    if (tid < 128) {
        int k = tid >> 5, d2 = tid & 31;
        float2 acc = make_float2(0.f, 0.f);
#pragma unroll
        for (int s = 0; s < S_; s++) {
            float m = mulp[k][s];
            float2 x = *reinterpret_cast<const float2*>(&xu[s][2 * d2]);
            acc.x = fmaf(m, x.x, acc.x);
            acc.y = fmaf(m, x.y, acc.y);
        }
        *reinterpret_cast<float2*>(&delta[k][2 * d2]) = acc;
    }
    {
        int k = w & 3;
        int e0 = (w >> 2) * 32 + lane;
        float acc = 0.f;
#pragma unroll 8
        for (int d = 0; d < D_; d++)
            acc = fmaf(Cu[k][d], __ldg(&w3[d * D_ + e0]), acc);
        cw3[k][e0] = acc;
    }
    __syncthreads();

    // ---- normalize delta ----
    if (w < K_) {
        int k = w;
        float d0 = delta[k][lane], d1 = delta[k][lane + 32];
        float n = warpsum(d0 * d0 + d1 * d1);
        if (lane == 0) nrm2[k] = 1.f / fmaxf(sqrtf(n), 1e-12f);
    }
    __syncthreads();
    {
        int k = tid >> 6, d = tid & 63;
        delta[k][d] *= nrm2[k];
    }

    // ---- logit2[s] via rank-4 combine ----
    {
        const float w4a = __ldg(&w4[2 * lane]);
        const float w4b = __ldg(&w4[2 * lane + 1]);
        float c0a = cw3[0][2*lane], c0b = cw3[0][2*lane+1];
        float c1a = cw3[1][2*lane], c1b = cw3[1][2*lane+1];
        float c2a = cw3[2][2*lane], c2b = cw3[2][2*lane+1];
        float c3a = cw3[3][2*lane], c3b = cw3[3][2*lane+1];
#pragma unroll
        for (int c = 0; c < 7; c++) {
            int s = w + 8 * c;
            if (s < S_) {
                float p0 = Pktb[s][0], p1 = Pktb[s][1], p2 = Pktb[s][2], p3 = Pktb[s][3];
                float a0 = p0*c0a + p1*c1a + p2*c2a + p3*c3a;
                float a1 = p0*c0b + p1*c1b + p2*c2b + p3*c3b;
                float t = tanhf(a0) * w4a + tanhf(a1) * w4b;
                t = warpsum(t);
                if (lane == 0) logit[s] = t;
            }
        }
    }
    __syncthreads();
    if (w == 0) {
        float v0 = (lane < S_) ? logit[lane] : -1e30f;
        float v1 = (lane + 32 < S_) ? logit[lane + 32] : -1e30f;
        float m = warpmax(fmaxf(v0, v1));
        float e0 = (lane < S_) ? expf(v0 - m) : 0.f;
        float e1 = (lane + 32 < S_) ? expf(v1 - m) : 0.f;
        float inv = 1.f / warpsum(e0 + e1);
        if (lane < S_) aw[lane] = e0 * inv;
        if (lane + 32 < S_) aw[lane + 32] = e1 * inv;
    }
    __syncthreads();

    // ---- pk[k]; capt ----
    if (w < K_) {
        int k = w;
        float p = ((lane < S_) ? aw[lane] * Pktb[lane][k] : 0.f)
                + ((lane + 32 < S_) ? aw[lane + 32] * Pktb[lane + 32][k] : 0.f);
        p = warpsum(p);
        if (lane == 0) pks[k] = p;
    }
    __syncthreads();
    if (tid < D_) {
        capt[tid] = pks[0]*Cu[0][tid] + pks[1]*Cu[1][tid]
                  + pks[2]*Cu[2][tid] + pks[3]*Cu[3][tid];
    }
    __syncthreads();
    if (w == 0) {
        float c0 = capt[lane], c1 = capt[lane + 32];
        float mean = warpsum(c0 + c1) * (1.f / 64.f);
        float d0 = c0 - mean, d1 = c1 - mean;
        float var = warpsum(d0 * d0 + d1 * d1) * (1.f / 64.f);
        float inv = rsqrtf(var + LN_EPS);
        capt[lane]      = d0 * inv * __ldg(&ln4w[lane])      + __ldg(&ln4b[lane]);
        capt[lane + 32] = d1 * inv * __ldg(&ln4w[lane + 32]) + __ldg(&ln4b[lane + 32]);
    }
    __syncthreads();

    // ---- e_k softmax; v_u ----
    if (w < K_) {
        int k = w;
        float p = delta[k][lane] * capt[lane] + delta[k][lane + 32] * capt[lane + 32];
        p = warpsum(p) * (1.f / TAU_);
        if (lane == 0) ekw[k] = p;
    }
    __syncthreads();
    if (tid == 0) {
        float m = fmaxf(fmaxf(ekw[0], ekw[1]), fmaxf(ekw[2], ekw[3]));
        float e0 = expf(ekw[0] - m), e1 = expf(ekw[1] - m);
        float e2 = expf(ekw[2] - m), e3 = expf(ekw[3] - m);
        float inv = 1.f / (e0 + e1 + e2 + e3);
        ekw[0] = e0 * inv; ekw[1] = e1 * inv; ekw[2] = e2 * inv; ekw[3] = e3 * inv;
    }
    __syncthreads();
    if (tid < D_) {
        vstage[tid] = ekw[0] * delta[0][tid] + ekw[1] * delta[1][tid]
                    + ekw[2] * delta[2][tid] + ekw[3] * delta[3][tid];
    }
    __syncthreads();
    if (tid < 32) {
        int j = tid;
        float v0 = vstage[2 * j], v1 = vstage[2 * j + 1];
        __nv_bfloat16 h0 = __float2bfloat16(v0), h1 = __float2bfloat16(v1);
        uint32_t hw = pack_bf16(v0, v1);
        uint32_t lw = pack_bf16(v0 - __bfloat162float(h0), v1 - __bfloat162float(h1));
        int rt = b >> 4, rr = b & 15;
        int role = rr >> 3, lg2 = rr & 7;
        int kk = j >> 3, t = j & 7, q2 = t & 3, h8 = t >> 2;
        int lane2 = lg2 * 4 + q2;
        int slot = role + 2 * h8;
        int frag = (rt * 4 + kk) * 32 + lane2;
        reinterpret_cast<uint32_t*>(&g_vufh[frag])[slot] = hw;
        reinterpret_cast<uint32_t*>(&g_vufl[frag])[slot] = lw;
    }
}

// ---------------------------------------------------------------------------
// Kernel 4: scores — round-11 exact (register-resident B, 128 thr, MSPLIT=2).
// ---------------------------------------------------------------------------
#define BSTR2 72
#define MSPLIT 2
__global__ __launch_bounds__(128) void scores_frag(
    const float* __restrict__ item_emb,
    float* __restrict__ out)
{
    __shared__ __align__(16) __nv_bfloat16 bh[32 * BSTR2];
    __shared__ __align__(16) __nv_bfloat16 bl[32 * BSTR2];

    const int tid = threadIdx.x, lane = tid & 31, wm = tid >> 5;
    const int nbase = blockIdx.x * 32;

    for (int i = tid; i < 512; i += 128) {
        int row = i >> 4, q4 = i & 15;
        float4 v = __ldg(&reinterpret_cast<const float4*>(
            item_emb + (size_t)(nbase + row) * D_)[q4]);
        uint32_t h0 = pack_bf16(v.x, v.y), h1 = pack_bf16(v.z, v.w);
        __nv_bfloat162 b0 = *reinterpret_cast<__nv_bfloat162*>(&h0);
        __nv_bfloat162 b1 = *reinterpret_cast<__nv_bfloat162*>(&h1);
        uint32_t l0 = pack_bf16(v.x - __bfloat162float(b0.x), v.y - __bfloat162float(b0.y));
        uint32_t l1 = pack_bf16(v.z - __bfloat162float(b1.x), v.w - __bfloat162float(b1.y));
        *reinterpret_cast<uint2*>(&bh[row * BSTR2 + q4 * 4]) = make_uint2(h0, h1);
        *reinterpret_cast<uint2*>(&bl[row * BSTR2 + q4 * 4]) = make_uint2(l0, l1);
    }
    __syncthreads();

    const int lg = lane >> 2, q = lane & 3;
    const int rig = lane & 7, mcode = lane >> 3;
    const int j_off = mcode >> 1, khalf = mcode & 1;
    uint32_t bhb = (uint32_t)__cvta_generic_to_shared(bh)
                 + ((j_off * 8 + rig) * BSTR2 + khalf * 8) * 2;
    uint32_t blb = (uint32_t)__cvta_generic_to_shared(bl)
                 + ((j_off * 8 + rig) * BSTR2 + khalf * 8) * 2;

    uint32_t Bfh[4][4][2], Bfl[4][4][2];
#pragma unroll
    for (int kk = 0; kk < 4; kk++)
#pragma unroll
        for (int p = 0; p < 2; p++) {
            uint32_t off = (uint32_t)(p * 16 * BSTR2 * 2 + kk * 32);
            LDSM4(Bfh[kk][2*p][0], Bfh[kk][2*p][1], Bfh[kk][2*p+1][0], Bfh[kk][2*p+1][1], bhb + off);
            LDSM4(Bfl[kk][2*p][0], Bfl[kk][2*p][1], Bfl[kk][2*p+1][0], Bfl[kk][2*p+1][1], blb + off);
        }

    const int mt0 = blockIdx.y * (16 / MSPLIT);
    for (int mt = mt0; mt < mt0 + 16 / MSPLIT; mt++) {
        float acc[2][4][4];
#pragma unroll
        for (int f = 0; f < 2; f++)
#pragma unroll
            for (int j = 0; j < 4; j++) {
                acc[f][j][0]=0.f; acc[f][j][1]=0.f; acc[f][j][2]=0.f; acc[f][j][3]=0.f;
            }

        const int rt0 = mt * 8 + wm * 2;
#pragma unroll
        for (int kk = 0; kk < 4; kk++) {
            uint4 ah0 = g_vufh[(rt0 * 4 + kk) * 32 + lane];
            uint4 ah1 = g_vufh[((rt0 + 1) * 4 + kk) * 32 + lane];
            uint4 al0 = g_vufl[(rt0 * 4 + kk) * 32 + lane];
            uint4 al1 = g_vufl[((rt0 + 1) * 4 + kk) * 32 + lane];
#pragma unroll
            for (int j = 0; j < 4; j++) {
                MMA_BF16(acc[0][j][0],acc[0][j][1],acc[0][j][2],acc[0][j][3],
                         ah0.x,ah0.y,ah0.z,ah0.w, Bfh[kk][j][0],Bfh[kk][j][1]);
                MMA_BF16(acc[0][j][0],acc[0][j][1],acc[0][j][2],acc[0][j][3],
                         ah0.x,ah0.y,ah0.z,ah0.w, Bfl[kk][j][0],Bfl[kk][j][1]);
                MMA_BF16(acc[0][j][0],acc[0][j][1],acc[0][j][2],acc[0][j][3],
                         al0.x,al0.y,al0.z,al0.w, Bfh[kk][j][0],Bfh[kk][j][1]);
                MMA_BF16(acc[1][j][0],acc[1][j][1],acc[1][j][2],acc[1][j][3],
                         ah1.x,ah1.y,ah1.z,ah1.w, Bfh[kk][j][0],Bfh[kk][j][1]);
                MMA_BF16(acc[1][j][0],acc[1][j][1],acc[1][j][2],acc[1][j][3],
                         ah1.x,ah1.y,ah1.z,ah1.w, Bfl[kk][j][0],Bfl[kk][j][1]);
                MMA_BF16(acc[1][j][0],acc[1][j][1],acc[1][j][2],acc[1][j][3],
                         al1.x,al1.y,al1.z,al1.w, Bfh[kk][j][0],Bfh[kk][j][1]);
            }
        }

#pragma unroll
        for (int f = 0; f < 2; f++) {
            int r0 = mt * 128 + wm * 32 + f * 16 + lg;
#pragma unroll
            for (int j = 0; j < 4; j++) {
                int n0 = nbase + j * 8 + 2 * q;
                __stcs(reinterpret_cast<float2*>(out + (size_t)r0 * N_ + n0),
                       make_float2(acc[f][j][0], acc[f][j][1]));
                __stcs(reinterpret_cast<float2*>(out + (size_t)(r0 + 8) * N_ + n0),
                       make_float2(acc[f][j][2], acc[f][j][3]));
            }
        }
    }
}

extern "C" void kernel_launch(void* const* d_in, const int* in_sizes, int n_in,
                              void* d_out, int out_size) {
    const int* item_seq = (const int*)d_in[0];
    const float* item_emb = (const float*)d_in[2];
    const float* Cg  = (const float*)d_in[3];
    const float* w1  = (const float*)d_in[4];
    const float* w2  = (const float*)d_in[5];
    const float* w3  = (const float*)d_in[6];
    const float* w4  = (const float*)d_in[7];
    const float* wk1 = (const float*)d_in[8];
    const float* wk2 = (const float*)d_in[9];
    const float* ln2w = (const float*)d_in[10];
    const float* ln2b = (const float*)d_in[11];
    const float* ln4w = (const float*)d_in[12];
    const float* ln4b = (const float*)d_in[13];
    float* out = (float*)d_out;

    wprep_kernel<<<6, 256>>>(wk1, w1, w3);
    rowgemm_kernel<<<ROWS_ / 128, 256>>>(item_seq, item_emb, wk2, w2);
    zu_kernel<<<B_, 64>>>(item_seq, item_emb);
    su_kernel<<<B_ / 16, 256>>>(Cg);
    head_kernel<<<B_, 256>>>(item_seq, item_emb, Cg, w3, w4,
                             ln2w, ln2b, ln4w, ln4b);
    dim3 sg(N_ / 32, MSPLIT);
    scores_frag<<<sg, 128>>>(item_emb, out);
}

// round 17
// speedup vs baseline: 1.3790x; 1.0234x over previous
#include <cuda_runtime.h>
#include <cuda_bf16.h>
#include <cstdint>

#define B_ 2048
#define S_ 50
#define D_ 64
#define L_ 500
#define K_ 4
#define N_ 100000
#define TAU_ 0.1f
#define LN_EPS 1e-12f
#define ROWS_ (B_ * S_)

// v_u in MMA-fragment order (hi/lo): [rowtile 128][kk 4][lane 32] each uint4
__device__ uint4 g_vufh[128 * 4 * 32];
__device__ uint4 g_vufl[128 * 4 * 32];
// rowgemm outputs
__device__ float g_aklog[K_ * ROWS_];
__device__ float g_logit[ROWS_];
__device__ float g_w3n[ROWS_ * D_];
// zu / su
__device__ float g_zu[B_ * D_];
__device__ float g_su[B_ * L_];
// pre-transposed bf16 hi/lo weights: [widx][e][d] (widx: wk1[0..3], w1, w3)
__device__ __nv_bfloat16 g_wbh[6 * 4096];
__device__ __nv_bfloat16 g_wbl[6 * 4096];

__device__ __forceinline__ float warpsum(float v) {
#pragma unroll
    for (int o = 16; o; o >>= 1) v += __shfl_xor_sync(0xffffffffu, v, o);
    return v;
}
__device__ __forceinline__ float warpmax(float v) {
#pragma unroll
    for (int o = 16; o; o >>= 1) v = fmaxf(v, __shfl_xor_sync(0xffffffffu, v, o));
    return v;
}
__device__ __forceinline__ uint32_t pack_bf16(float a, float b) {
    __nv_bfloat162 t = __floats2bfloat162_rn(a, b);
    return *reinterpret_cast<uint32_t*>(&t);
}

#define MMA_BF16(d0,d1,d2,d3,a0,a1,a2,a3,b0,b1)                              \
    asm volatile("mma.sync.aligned.m16n8k16.row.col.f32.bf16.bf16.f32 "      \
        "{%0,%1,%2,%3}, {%4,%5,%6,%7}, {%8,%9}, {%0,%1,%2,%3};"              \
        : "+f"(d0), "+f"(d1), "+f"(d2), "+f"(d3)                             \
        : "r"(a0), "r"(a1), "r"(a2), "r"(a3), "r"(b0), "r"(b1))
#define LDSM4(r0,r1,r2,r3,addr)                                              \
    asm volatile("ldmatrix.sync.aligned.m8n8.x4.shared.b16 {%0,%1,%2,%3}, [%4];" \
        : "=r"(r0), "=r"(r1), "=r"(r2), "=r"(r3) : "r"(addr))

// ---------------------------------------------------------------------------
// Kernel -1: wprep — convert 6 weight matrices to transposed bf16 hi/lo.
// ---------------------------------------------------------------------------
__global__ __launch_bounds__(256) void wprep_kernel(
    const float* __restrict__ wk1, const float* __restrict__ w1,
    const float* __restrict__ w3)
{
    const int widx = blockIdx.x;
    const float* W = (widx < 4) ? (wk1 + widx * 4096) : (widx == 4 ? w1 : w3);
    __nv_bfloat16* dh = g_wbh + widx * 4096;
    __nv_bfloat16* dl = g_wbl + widx * 4096;
    for (int idx = threadIdx.x; idx < 4096; idx += 256) {
        int d = idx >> 6, e = idx & 63;
        float v = __ldg(&W[idx]);
        __nv_bfloat16 h = __float2bfloat16(v);
        dh[e * 64 + d] = h;
        dl[e * 64 + d] = __float2bfloat16(v - __bfloat162float(h));
    }
}

// ---------------------------------------------------------------------------
// Kernel 0: rowgemm (unchanged from round 16)
// ---------------------------------------------------------------------------
#define ASTR 72
__global__ __launch_bounds__(256) void rowgemm_kernel(
    const int* __restrict__ item_seq, const float* __restrict__ item_emb,
    const float* __restrict__ wk2, const float* __restrict__ w2)
{
    __shared__ __align__(16) __nv_bfloat16 Ah[128 * ASTR];
    __shared__ __align__(16) __nv_bfloat16 Al[128 * ASTR];
    __shared__ __align__(16) __nv_bfloat16 Bh[D_ * ASTR];
    __shared__ __align__(16) __nv_bfloat16 Bl[D_ * ASTR];
    __shared__ float wvec[D_];

    const int tid = threadIdx.x, lane = tid & 31, w = tid >> 5;
    const int rbase = blockIdx.x * 128;
    {
        int r = tid >> 1, h = tid & 1;
        int it = __ldg(&item_seq[rbase + r]);
        const float4* ep = reinterpret_cast<const float4*>(item_emb + (size_t)it * D_) + h * 8;
        uint32_t* dh = reinterpret_cast<uint32_t*>(Ah + r * ASTR + h * 32);
        uint32_t* dl = reinterpret_cast<uint32_t*>(Al + r * ASTR + h * 32);
#pragma unroll
        for (int i = 0; i < 8; i++) {
            float4 f = __ldg(&ep[i]);
            uint32_t h0 = pack_bf16(f.x, f.y), h1 = pack_bf16(f.z, f.w);
            __nv_bfloat162 b0 = *reinterpret_cast<__nv_bfloat162*>(&h0);
            __nv_bfloat162 b1 = *reinterpret_cast<__nv_bfloat162*>(&h1);
            dh[2*i] = h0; dh[2*i+1] = h1;
            dl[2*i]   = pack_bf16(f.x - __bfloat162float(b0.x), f.y - __bfloat162float(b0.y));
            dl[2*i+1] = pack_bf16(f.z - __bfloat162float(b1.x), f.w - __bfloat162float(b1.y));
        }
    }
    const int lg = lane >> 2, q = lane & 3;
    const int rig = lane & 7, mcode = lane >> 3;
    const int j_off = mcode >> 1, khalf = mcode & 1;
    const int mbase = w * 16;
    uint32_t aBh = (uint32_t)__cvta_generic_to_shared(Ah)
                 + ((mbase + (lane & 7) + ((lane >> 3) & 1) * 8) * ASTR + ((lane >> 4) * 8)) * 2;
    uint32_t aBl = (uint32_t)__cvta_generic_to_shared(Al)
                 + ((mbase + (lane & 7) + ((lane >> 3) & 1) * 8) * ASTR + ((lane >> 4) * 8)) * 2;
    uint32_t bBh = (uint32_t)__cvta_generic_to_shared(Bh)
                 + ((j_off * 8 + rig) * ASTR + khalf * 8) * 2;
    uint32_t bBl = (uint32_t)__cvta_generic_to_shared(Bl)
                 + ((j_off * 8 + rig) * ASTR + khalf * 8) * 2;
    const int r0g = rbase + mbase + lg, r1g = r0g + 8;

    for (int widx = 0; widx < 6; widx++) {
        __syncthreads();
        {
            const uint4* sH = reinterpret_cast<const uint4*>(g_wbh + widx * 4096);
            const uint4* sL = reinterpret_cast<const uint4*>(g_wbl + widx * 4096);
#pragma unroll
            for (int i = 0; i < 2; i++) {
                int idx = tid + i * 256;
                int e = idx >> 3, d8 = (idx & 7) * 8;
                *reinterpret_cast<uint4*>(&Bh[e * ASTR + d8]) = __ldg(&sH[idx]);
                *reinterpret_cast<uint4*>(&Bl[e * ASTR + d8]) = __ldg(&sL[idx]);
            }
        }
        if (tid < D_) {
            if (widx < 4)       wvec[tid] = __ldg(&wk2[widx * D_ + tid]);
            else if (widx == 4) wvec[tid] = __ldg(&w2[tid]);
        }
        __syncthreads();

        float acc[8][4];
#pragma unroll
        for (int j = 0; j < 8; j++) { acc[j][0]=0.f; acc[j][1]=0.f; acc[j][2]=0.f; acc[j][3]=0.f; }
#pragma unroll
        for (int kk = 0; kk < 4; kk++) {
            uint32_t ah0,ah1,ah2,ah3, al0,al1,al2,al3;
            LDSM4(ah0,ah1,ah2,ah3, aBh + kk * 32);
            LDSM4(al0,al1,al2,al3, aBl + kk * 32);
#pragma unroll
            for (int p = 0; p < 4; p++) {
                uint32_t b0h,b1h,b2h,b3h, b0l,b1l,b2l,b3l;
                uint32_t off = (uint32_t)(p * 16 * ASTR * 2 + kk * 32);
                LDSM4(b0h,b1h,b2h,b3h, bBh + off);
                LDSM4(b0l,b1l,b2l,b3l, bBl + off);
                int j0 = 2 * p, j1 = 2 * p + 1;
                MMA_BF16(acc[j0][0],acc[j0][1],acc[j0][2],acc[j0][3], ah0,ah1,ah2,ah3, b0h,b1h);
                MMA_BF16(acc[j0][0],acc[j0][1],acc[j0][2],acc[j0][3], ah0,ah1,ah2,ah3, b0l,b1l);
                MMA_BF16(acc[j0][0],acc[j0][1],acc[j0][2],acc[j0][3], al0,al1,al2,al3, b0h,b1h);
                MMA_BF16(acc[j1][0],acc[j1][1],acc[j1][2],acc[j1][3], ah0,ah1,ah2,ah3, b2h,b3h);
                MMA_BF16(acc[j1][0],acc[j1][1],acc[j1][2],acc[j1][3], ah0,ah1,ah2,ah3, b2l,b3l);
                MMA_BF16(acc[j1][0],acc[j1][1],acc[j1][2],acc[j1][3], al0,al1,al2,al3, b2h,b3h);
            }
        }
        if (widx < 5) {
            float s0 = 0.f, s1 = 0.f;
#pragma unroll
            for (int j = 0; j < 8; j++) {
                int e0 = j * 8 + 2 * q;
                float w0 = wvec[e0], w1v = wvec[e0 + 1];
                s0 += tanhf(acc[j][0]) * w0 + tanhf(acc[j][1]) * w1v;
                s1 += tanhf(acc[j][2]) * w0 + tanhf(acc[j][3]) * w1v;
            }
            s0 += __shfl_xor_sync(0xffffffffu, s0, 1);
            s0 += __shfl_xor_sync(0xffffffffu, s0, 2);
            s1 += __shfl_xor_sync(0xffffffffu, s1, 1);
            s1 += __shfl_xor_sync(0xffffffffu, s1, 2);
            if (q == 0) {
                if (widx < 4) { g_aklog[widx * ROWS_ + r0g] = s0; g_aklog[widx * ROWS_ + r1g] = s1; }
                else          { g_logit[r0g] = s0; g_logit[r1g] = s1; }
            }
        } else {
            float n0 = 0.f, n1 = 0.f;
#pragma unroll
            for (int j = 0; j < 8; j++) {
                n0 += acc[j][0]*acc[j][0] + acc[j][1]*acc[j][1];
                n1 += acc[j][2]*acc[j][2] + acc[j][3]*acc[j][3];
            }
            n0 += __shfl_xor_sync(0xffffffffu, n0, 1);
            n0 += __shfl_xor_sync(0xffffffffu, n0, 2);
            n1 += __shfl_xor_sync(0xffffffffu, n1, 1);
            n1 += __shfl_xor_sync(0xffffffffu, n1, 2);
            float inv0 = 1.f / fmaxf(sqrtf(n0), 1e-12f);
            float inv1 = 1.f / fmaxf(sqrtf(n1), 1e-12f);
#pragma unroll
            for (int j = 0; j < 8; j++) {
                int c0 = j * 8 + 2 * q;
                *reinterpret_cast<float2*>(g_w3n + (size_t)r0g * D_ + c0) =
                    make_float2(acc[j][0] * inv0, acc[j][1] * inv0);
                *reinterpret_cast<float2*>(g_w3n + (size_t)r1g * D_ + c0) =
                    make_float2(acc[j][2] * inv1, acc[j][3] * inv1);
            }
        }
    }
}

// ---------------------------------------------------------------------------
// Kernel 1: zu (unchanged)
// ---------------------------------------------------------------------------
__global__ __launch_bounds__(64) void zu_kernel(
    const int* __restrict__ item_seq, const float* __restrict__ item_emb)
{
    __shared__ float aw[S_];
    __shared__ int   seqs[S_];
    __shared__ __align__(16) float4 part[4][16];
    const int b = blockIdx.x, tid = threadIdx.x;
    if (tid < S_) seqs[tid] = __ldg(&item_seq[b * S_ + tid]);
    if (tid < 32) {
        const float* lp = g_logit + b * S_;
        float v0 = (tid < S_) ? lp[tid] : -1e30f;
        float v1 = (tid + 32 < S_) ? lp[tid + 32] : -1e30f;
        float m = warpmax(fmaxf(v0, v1));
        float e0 = (tid < S_) ? expf(v0 - m) : 0.f;
        float e1 = (tid + 32 < S_) ? expf(v1 - m) : 0.f;
        float inv = 1.f / warpsum(e0 + e1);
        if (tid < S_) aw[tid] = e0 * inv;
        if (tid + 32 < S_) aw[tid + 32] = e1 * inv;
    }
    __syncthreads();
    int qd = tid & 15, strip = tid >> 4;
    float4 acc = make_float4(0.f, 0.f, 0.f, 0.f);
    for (int s = strip; s < S_; s += 4) {
        const float4* xp = reinterpret_cast<const float4*>(item_emb + (size_t)seqs[s] * D_);
        float4 x = __ldg(&xp[qd]);
        float a = aw[s];
        acc.x = fmaf(a, x.x, acc.x); acc.y = fmaf(a, x.y, acc.y);
        acc.z = fmaf(a, x.z, acc.z); acc.w = fmaf(a, x.w, acc.w);
    }
    part[strip][qd] = acc;
    __syncthreads();
    if (tid < 16) {
        float4 a = part[0][tid], b1 = part[1][tid], c = part[2][tid], d = part[3][tid];
        reinterpret_cast<float4*>(g_zu + b * D_)[tid] =
            make_float4(a.x+b1.x+c.x+d.x, a.y+b1.y+c.y+d.y, a.z+b1.z+c.z+d.z, a.w+b1.w+c.w+d.w);
    }
}

// ---------------------------------------------------------------------------
// Kernel 2: su — L split 4 ways for occupancy. grid (128, 4).
// ---------------------------------------------------------------------------
__global__ __launch_bounds__(256) void su_kernel(const float* __restrict__ Cg)
{
    __shared__ __align__(16) float Zs[16][D_];
    const int tid = threadIdx.x, bbase = blockIdx.x * 16;
    const int lbase = blockIdx.y * 125;
    for (int i = tid; i < 16 * 16; i += 256) {
        int j = i >> 4, q = i & 15;
        reinterpret_cast<float4*>(&Zs[j][0])[q] =
            reinterpret_cast<const float4*>(g_zu + (bbase + j) * D_)[q];
    }
    __syncthreads();
    if (tid < 125) {
        int l = lbase + tid;
        float acc[16];
#pragma unroll
        for (int j = 0; j < 16; j++) acc[j] = 0.f;
        const float4* cr = reinterpret_cast<const float4*>(Cg + l * D_);
#pragma unroll
        for (int dq = 0; dq < 16; dq++) {
            float4 c = __ldg(&cr[dq]);
#pragma unroll
            for (int j = 0; j < 16; j++) {
                acc[j] = fmaf(c.x, Zs[j][4*dq],   acc[j]);
                acc[j] = fmaf(c.y, Zs[j][4*dq+1], acc[j]);
                acc[j] = fmaf(c.z, Zs[j][4*dq+2], acc[j]);
                acc[j] = fmaf(c.w, Zs[j][4*dq+3], acc[j]);
            }
        }
#pragma unroll
        for (int j = 0; j < 16; j++) g_su[(bbase + j) * L_ + l] = acc[j];
    }
}

// ---------------------------------------------------------------------------
// Kernel 3: head — buf2 staging removed; P_k_t reads g_w3n directly.
// ---------------------------------------------------------------------------
__global__ __launch_bounds__(256) void head_kernel(
    const int* __restrict__ item_seq, const float* __restrict__ item_emb,
    const float* __restrict__ Cg,
    const float* __restrict__ w3, const float* __restrict__ w4,
    const float* __restrict__ ln2w, const float* __restrict__ ln2b,
    const float* __restrict__ ln4w, const float* __restrict__ ln4b)
{
    __shared__ __align__(16) float xu[S_][D_];
    __shared__ int   seqs[S_];
    __shared__ float logit[S_];
    __shared__ float aw[S_];
    __shared__ __align__(16) float su[L_];
    __shared__ float candv[16];
    __shared__ int   candi[16];
    __shared__ float stopv[K_];
    __shared__ int   sidx[K_];
    __shared__ __align__(16) float Cu[K_][D_];
    __shared__ __align__(16) float Cun[K_][D_];
    __shared__ __align__(16) float Pktb[S_][K_];
    __shared__ float mulp[K_][S_];
    __shared__ __align__(16) float delta[K_][D_];
    __shared__ float nrm2[K_];
    __shared__ float capt[D_];
    __shared__ float ekw[K_];
    __shared__ float vstage[D_];
    __shared__ float cw3[K_][D_];
    __shared__ float pks[K_];

    const int b = blockIdx.x, tid = threadIdx.x, lane = tid & 31, w = tid >> 5;

    if (tid < S_) seqs[tid] = __ldg(&item_seq[b * S_ + tid]);
    if (tid < 125)
        reinterpret_cast<float4*>(su)[tid] =
            __ldg(&reinterpret_cast<const float4*>(g_su + b * L_)[tid]);
    __syncthreads();
    for (int i = tid; i < S_ * 16; i += 256) {
        int s = i >> 4, q = i & 15;
        const float4* ep = reinterpret_cast<const float4*>(item_emb + (size_t)seqs[s] * D_);
        reinterpret_cast<float4*>(&xu[s][0])[q] = __ldg(&ep[q]);
    }
    __syncthreads();

    // ---- top-4, stage 1: warps 0-3 each find top-4 of a 125-element part ----
    if (w < 4) {
        const int base = w * 125;
        float lv[4]; int li[4];
#pragma unroll
        for (int r = 0; r < 4; r++) {
            float mv = -1e30f; int mi = -1;
            for (int l = base + lane; l < base + 125; l += 32) {
                bool skip = false;
#pragma unroll
                for (int t = 0; t < 4; t++)
                    if (t < r && li[t] == l) skip = true;
                float v = su[l];
                if (!skip && (v > mv || (v == mv && l > mi))) { mv = v; mi = l; }
            }
#pragma unroll
            for (int o = 16; o; o >>= 1) {
                float ov = __shfl_xor_sync(0xffffffffu, mv, o);
                int   oi = __shfl_xor_sync(0xffffffffu, mi, o);
                if (ov > mv || (ov == mv && oi > mi)) { mv = ov; mi = oi; }
            }
            lv[r] = mv; li[r] = mi;
        }
        if (lane < 4) { candv[w * 4 + lane] = lv[lane]; candi[w * 4 + lane] = li[lane]; }
    }
    __syncthreads();
    // ---- stage 2: warp 0 selects global top-4 from 16 candidates ----
    if (w == 0) {
        float cv = (lane < 16) ? candv[lane] : -1e30f;
        int   ci = (lane < 16) ? candi[lane] : -1;
#pragma unroll
        for (int r = 0; r < 4; r++) {
            float mv = cv; int mi = ci;
#pragma unroll
            for (int o = 16; o; o >>= 1) {
                float ov = __shfl_xor_sync(0xffffffffu, mv, o);
                int   oi = __shfl_xor_sync(0xffffffffu, mi, o);
                if (ov > mv || (ov == mv && oi > mi)) { mv = ov; mi = oi; }
            }
            if (ci == mi && ci >= 0) { cv = -1e30f; ci = -1; }
            if (lane == 0) { sidx[3 - r] = mi; stopv[3 - r] = mv; }
        }
    }
    __syncthreads();

    // ---- C_u, C_u_norm ----
    if (w < K_) {
        int k = w;
        float sg = 1.f / (1.f + expf(-stopv[k]));
        const float* cr = Cg + sidx[k] * D_;
        float v0 = __ldg(&cr[lane]) * sg;
        float v1 = __ldg(&cr[lane + 32]) * sg;
        Cu[k][lane] = v0; Cu[k][lane + 32] = v1;
        float mean = warpsum(v0 + v1) * (1.f / 64.f);
        float d0 = v0 - mean, d1 = v1 - mean;
        float var = warpsum(d0 * d0 + d1 * d1) * (1.f / 64.f);
        float inv = rsqrtf(var + LN_EPS);
        Cun[k][lane]      = d0 * inv * __ldg(&ln2w[lane])      + __ldg(&ln2b[lane]);
        Cun[k][lane + 32] = d1 * inv * __ldg(&ln2w[lane + 32]) + __ldg(&ln2b[lane + 32]);
    }
    __syncthreads();

    // ---- P_k_t (reads g_w3n directly) + softmax over k ----
    if (tid < S_ * K_) {
        int s = tid >> 2, k = tid & 3;
        const float4* bp = reinterpret_cast<const float4*>(
            g_w3n + (size_t)(b * S_ + s) * D_);
        const float4* cp = reinterpret_cast<const float4*>(&Cun[k][0]);
        float acc = 0.f;
#pragma unroll
        for (int q = 0; q < 16; q++) {
            float4 x = __ldg(&bp[q]);
            float4 c = cp[q];
            acc += x.x*c.x + x.y*c.y + x.z*c.z + x.w*c.w;
        }
        Pktb[s][k] = acc;
    }
    __syncthreads();
    if (tid < S_) {
        float v0 = Pktb[tid][0], v1 = Pktb[tid][1], v2 = Pktb[tid][2], v3 = Pktb[tid][3];
        float m = fmaxf(fmaxf(v0, v1), fmaxf(v2, v3));
        float e0 = expf(v0 - m), e1 = expf(v1 - m), e2 = expf(v2 - m), e3 = expf(v3 - m);
        float inv = 1.f / (e0 + e1 + e2 + e3);
        Pktb[tid][0] = e0 * inv; Pktb[tid][1] = e1 * inv;
        Pktb[tid][2] = e2 * inv; Pktb[tid][3] = e3 * inv;
    }
    __syncthreads();

    // ---- P_t_k softmax from aklog; mulp ----
    if (w < K_) {
        int k = w;
        const float* akr = g_aklog + k * ROWS_ + b * S_;
        float v0 = (lane < S_) ? akr[lane] : -1e30f;
        float v1 = (lane + 32 < S_) ? akr[lane + 32] : -1e30f;
        float m = warpmax(fmaxf(v0, v1));
        float e0 = (lane < S_) ? expf(v0 - m) : 0.f;
        float e1 = (lane + 32 < S_) ? expf(v1 - m) : 0.f;
        float inv = 1.f / warpsum(e0 + e1);
        if (lane < S_) mulp[k][lane] = Pktb[lane][k] * e0 * inv;
        if (lane + 32 < S_) mulp[k][lane + 32] = Pktb[lane + 32][k] * e1 * inv;
    }
    __syncthreads();

    // ---- delta_raw (warps 0-3) + cw3 = Cu @ w3 (all 8 warps) ----
    if (tid < 128) {
        int k = tid >> 5, d2 = tid & 31;
        float2 acc = make_float2(0.f, 0.f);
#pragma unroll
        for (int s = 0; s < S_; s++) {
            float m = mulp[k][s];
            float2 x = *reinterpret_cast<const float2*>(&xu[s][2 * d2]);
            acc.x = fmaf(m, x.x, acc.x);
            acc.y = fmaf(m, x.y, acc.y);
        }
        *reinterpret_cast<float2*>(&delta[k][2 * d2]) = acc;
    }
    {
        int k = w & 3;
        int e0 = (w >> 2) * 32 + lane;
        float acc = 0.f;
#pragma unroll 8
        for (int d = 0; d < D_; d++)
            acc = fmaf(Cu[k][d], __ldg(&w3[d * D_ + e0]), acc);
        cw3[k][e0] = acc;
    }
    __syncthreads();

    // ---- normalize delta ----
    if (w < K_) {
        int k = w;
        float d0 = delta[k][lane], d1 = delta[k][lane + 32];
        float n = warpsum(d0 * d0 + d1 * d1);
        if (lane == 0) nrm2[k] = 1.f / fmaxf(sqrtf(n), 1e-12f);
    }
    __syncthreads();
    {
        int k = tid >> 6, d = tid & 63;
        delta[k][d] *= nrm2[k];
    }

    // ---- logit2[s] via rank-4 combine ----
    {
        const float w4a = __ldg(&w4[2 * lane]);
        const float w4b = __ldg(&w4[2 * lane + 1]);
        float c0a = cw3[0][2*lane], c0b = cw3[0][2*lane+1];
        float c1a = cw3[1][2*lane], c1b = cw3[1][2*lane+1];
        float c2a = cw3[2][2*lane], c2b = cw3[2][2*lane+1];
        float c3a = cw3[3][2*lane], c3b = cw3[3][2*lane+1];
#pragma unroll
        for (int c = 0; c < 7; c++) {
            int s = w + 8 * c;
            if (s < S_) {
                float p0 = Pktb[s][0], p1 = Pktb[s][1], p2 = Pktb[s][2], p3 = Pktb[s][3];
                float a0 = p0*c0a + p1*c1a + p2*c2a + p3*c3a;
                float a1 = p0*c0b + p1*c1b + p2*c2b + p3*c3b;
                float t = tanhf(a0) * w4a + tanhf(a1) * w4b;
                t = warpsum(t);
                if (lane == 0) logit[s] = t;
            }
        }
    }
    __syncthreads();
    if (w == 0) {
        float v0 = (lane < S_) ? logit[lane] : -1e30f;
        float v1 = (lane + 32 < S_) ? logit[lane + 32] : -1e30f;
        float m = warpmax(fmaxf(v0, v1));
        float e0 = (lane < S_) ? expf(v0 - m) : 0.f;
        float e1 = (lane + 32 < S_) ? expf(v1 - m) : 0.f;
        float inv = 1.f / warpsum(e0 + e1);
        if (lane < S_) aw[lane] = e0 * inv;
        if (lane + 32 < S_) aw[lane + 32] = e1 * inv;
    }
    __syncthreads();

    // ---- pk[k]; capt ----
    if (w < K_) {
        int k = w;
        float p = ((lane < S_) ? aw[lane] * Pktb[lane][k] : 0.f)
                + ((lane + 32 < S_) ? aw[lane + 32] * Pktb[lane + 32][k] : 0.f);
        p = warpsum(p);
        if (lane == 0) pks[k] = p;
    }
    __syncthreads();
    if (tid < D_) {
        capt[tid] = pks[0]*Cu[0][tid] + pks[1]*Cu[1][tid]
                  + pks[2]*Cu[2][tid] + pks[3]*Cu[3][tid];
    }
    __syncthreads();
    if (w == 0) {
        float c0 = capt[lane], c1 = capt[lane + 32];
        float mean = warpsum(c0 + c1) * (1.f / 64.f);
        float d0 = c0 - mean, d1 = c1 - mean;
        float var = warpsum(d0 * d0 + d1 * d1) * (1.f / 64.f);
        float inv = rsqrtf(var + LN_EPS);
        capt[lane]      = d0 * inv * __ldg(&ln4w[lane])      + __ldg(&ln4b[lane]);
        capt[lane + 32] = d1 * inv * __ldg(&ln4w[lane + 32]) + __ldg(&ln4b[lane + 32]);
    }
    __syncthreads();

    // ---- e_k softmax; v_u ----
    if (w < K_) {
        int k = w;
        float p = delta[k][lane] * capt[lane] + delta[k][lane + 32] * capt[lane + 32];
        p = warpsum(p) * (1.f / TAU_);
        if (lane == 0) ekw[k] = p;
    }
    __syncthreads();
    if (tid == 0) {
        float m = fmaxf(fmaxf(ekw[0], ekw[1]), fmaxf(ekw[2], ekw[3]));
        float e0 = expf(ekw[0] - m), e1 = expf(ekw[1] - m);
        float e2 = expf(ekw[2] - m), e3 = expf(ekw[3] - m);
        float inv = 1.f / (e0 + e1 + e2 + e3);
        ekw[0] = e0 * inv; ekw[1] = e1 * inv; ekw[2] = e2 * inv; ekw[3] = e3 * inv;
    }
    __syncthreads();
    if (tid < D_) {
        vstage[tid] = ekw[0] * delta[0][tid] + ekw[1] * delta[1][tid]
                    + ekw[2] * delta[2][tid] + ekw[3] * delta[3][tid];
    }
    __syncthreads();
    if (tid < 32) {
        int j = tid;
        float v0 = vstage[2 * j], v1 = vstage[2 * j + 1];
        __nv_bfloat16 h0 = __float2bfloat16(v0), h1 = __float2bfloat16(v1);
        uint32_t hw = pack_bf16(v0, v1);
        uint32_t lw = pack_bf16(v0 - __bfloat162float(h0), v1 - __bfloat162float(h1));
        int rt = b >> 4, rr = b & 15;
        int role = rr >> 3, lg2 = rr & 7;
        int kk = j >> 3, t = j & 7, q2 = t & 3, h8 = t >> 2;
        int lane2 = lg2 * 4 + q2;
        int slot = role + 2 * h8;
        int frag = (rt * 4 + kk) * 32 + lane2;
        reinterpret_cast<uint32_t*>(&g_vufh[frag])[slot] = hw;
        reinterpret_cast<uint32_t*>(&g_vufl[frag])[slot] = lw;
    }
}

// ---------------------------------------------------------------------------
// Kernel 4: scores — round-11 exact (register-resident B, 128 thr, MSPLIT=2).
// ---------------------------------------------------------------------------
#define BSTR2 72
#define MSPLIT 2
__global__ __launch_bounds__(128) void scores_frag(
    const float* __restrict__ item_emb,
    float* __restrict__ out)
{
    __shared__ __align__(16) __nv_bfloat16 bh[32 * BSTR2];
    __shared__ __align__(16) __nv_bfloat16 bl[32 * BSTR2];

    const int tid = threadIdx.x, lane = tid & 31, wm = tid >> 5;
    const int nbase = blockIdx.x * 32;

    for (int i = tid; i < 512; i += 128) {
        int row = i >> 4, q4 = i & 15;
        float4 v = __ldg(&reinterpret_cast<const float4*>(
            item_emb + (size_t)(nbase + row) * D_)[q4]);
        uint32_t h0 = pack_bf16(v.x, v.y), h1 = pack_bf16(v.z, v.w);
        __nv_bfloat162 b0 = *reinterpret_cast<__nv_bfloat162*>(&h0);
        __nv_bfloat162 b1 = *reinterpret_cast<__nv_bfloat162*>(&h1);
        uint32_t l0 = pack_bf16(v.x - __bfloat162float(b0.x), v.y - __bfloat162float(b0.y));
        uint32_t l1 = pack_bf16(v.z - __bfloat162float(b1.x), v.w - __bfloat162float(b1.y));
        *reinterpret_cast<uint2*>(&bh[row * BSTR2 + q4 * 4]) = make_uint2(h0, h1);
        *reinterpret_cast<uint2*>(&bl[row * BSTR2 + q4 * 4]) = make_uint2(l0, l1);
    }
    __syncthreads();

    const int lg = lane >> 2, q = lane & 3;
    const int rig = lane & 7, mcode = lane >> 3;
    const int j_off = mcode >> 1, khalf = mcode & 1;
    uint32_t bhb = (uint32_t)__cvta_generic_to_shared(bh)
                 + ((j_off * 8 + rig) * BSTR2 + khalf * 8) * 2;
    uint32_t blb = (uint32_t)__cvta_generic_to_shared(bl)
                 + ((j_off * 8 + rig) * BSTR2 + khalf * 8) * 2;

    uint32_t Bfh[4][4][2], Bfl[4][4][2];
#pragma unroll
    for (int kk = 0; kk < 4; kk++)
#pragma unroll
        for (int p = 0; p < 2; p++) {
            uint32_t off = (uint32_t)(p * 16 * BSTR2 * 2 + kk * 32);
            LDSM4(Bfh[kk][2*p][0], Bfh[kk][2*p][1], Bfh[kk][2*p+1][0], Bfh[kk][2*p+1][1], bhb + off);
            LDSM4(Bfl[kk][2*p][0], Bfl[kk][2*p][1], Bfl[kk][2*p+1][0], Bfl[kk][2*p+1][1], blb + off);
        }

    const int mt0 = blockIdx.y * (16 / MSPLIT);
    for (int mt = mt0; mt < mt0 + 16 / MSPLIT; mt++) {
        float acc[2][4][4];
#pragma unroll
        for (int f = 0; f < 2; f++)
#pragma unroll
            for (int j = 0; j < 4; j++) {
                acc[f][j][0]=0.f; acc[f][j][1]=0.f; acc[f][j][2]=0.f; acc[f][j][3]=0.f;
            }

        const int rt0 = mt * 8 + wm * 2;
#pragma unroll
        for (int kk = 0; kk < 4; kk++) {
            uint4 ah0 = g_vufh[(rt0 * 4 + kk) * 32 + lane];
            uint4 ah1 = g_vufh[((rt0 + 1) * 4 + kk) * 32 + lane];
            uint4 al0 = g_vufl[(rt0 * 4 + kk) * 32 + lane];
            uint4 al1 = g_vufl[((rt0 + 1) * 4 + kk) * 32 + lane];
#pragma unroll
            for (int j = 0; j < 4; j++) {
                MMA_BF16(acc[0][j][0],acc[0][j][1],acc[0][j][2],acc[0][j][3],
                         ah0.x,ah0.y,ah0.z,ah0.w, Bfh[kk][j][0],Bfh[kk][j][1]);
                MMA_BF16(acc[0][j][0],acc[0][j][1],acc[0][j][2],acc[0][j][3],
                         ah0.x,ah0.y,ah0.z,ah0.w, Bfl[kk][j][0],Bfl[kk][j][1]);
                MMA_BF16(acc[0][j][0],acc[0][j][1],acc[0][j][2],acc[0][j][3],
                         al0.x,al0.y,al0.z,al0.w, Bfh[kk][j][0],Bfh[kk][j][1]);
                MMA_BF16(acc[1][j][0],acc[1][j][1],acc[1][j][2],acc[1][j][3],
                         ah1.x,ah1.y,ah1.z,ah1.w, Bfh[kk][j][0],Bfh[kk][j][1]);
                MMA_BF16(acc[1][j][0],acc[1][j][1],acc[1][j][2],acc[1][j][3],
                         ah1.x,ah1.y,ah1.z,ah1.w, Bfl[kk][j][0],Bfl[kk][j][1]);
                MMA_BF16(acc[1][j][0],acc[1][j][1],acc[1][j][2],acc[1][j][3],
                         al1.x,al1.y,al1.z,al1.w, Bfh[kk][j][0],Bfh[kk][j][1]);
            }
        }

#pragma unroll
        for (int f = 0; f < 2; f++) {
            int r0 = mt * 128 + wm * 32 + f * 16 + lg;
#pragma unroll
            for (int j = 0; j < 4; j++) {
                int n0 = nbase + j * 8 + 2 * q;
                __stcs(reinterpret_cast<float2*>(out + (size_t)r0 * N_ + n0),
                       make_float2(acc[f][j][0], acc[f][j][1]));
                __stcs(reinterpret_cast<float2*>(out + (size_t)(r0 + 8) * N_ + n0),
                       make_float2(acc[f][j][2], acc[f][j][3]));
            }
        }
    }
}

extern "C" void kernel_launch(void* const* d_in, const int* in_sizes, int n_in,
                              void* d_out, int out_size) {
    const int* item_seq = (const int*)d_in[0];
    const float* item_emb = (const float*)d_in[2];
    const float* Cg  = (const float*)d_in[3];
    const float* w1  = (const float*)d_in[4];
    const float* w2  = (const float*)d_in[5];
    const float* w3  = (const float*)d_in[6];
    const float* w4  = (const float*)d_in[7];
    const float* wk1 = (const float*)d_in[8];
    const float* wk2 = (const float*)d_in[9];
    const float* ln2w = (const float*)d_in[10];
    const float* ln2b = (const float*)d_in[11];
    const float* ln4w = (const float*)d_in[12];
    const float* ln4b = (const float*)d_in[13];
    float* out = (float*)d_out;

    wprep_kernel<<<6, 256>>>(wk1, w1, w3);
    rowgemm_kernel<<<ROWS_ / 128, 256>>>(item_seq, item_emb, wk2, w2);
    zu_kernel<<<B_, 64>>>(item_seq, item_emb);
    dim3 sug(B_ / 16, 4);
    su_kernel<<<sug, 256>>>(Cg);
    head_kernel<<<B_, 256>>>(item_seq, item_emb, Cg, w3, w4,
                             ln2w, ln2b, ln4w, ln4b);
    dim3 sg(N_ / 32, MSPLIT);
    scores_frag<<<sg, 128>>>(item_emb, out);
}